// round 1
// baseline (speedup 1.0000x reference)
#include <cuda_runtime.h>

#define BB 4
#define CC 256
#define NN 4096

// Scratch (allocation-free: __device__ bss)
__device__ float g_q[(size_t)BB * NN * CC];
__device__ float g_k[(size_t)BB * NN * CC];
__device__ float g_v[(size_t)BB * NN * CC];
__device__ float g_s[(size_t)BB * NN * NN];   // 256 MB scores
__device__ float g_m[BB * NN];
__device__ float g_li[BB * NN];
__device__ float g_o[(size_t)BB * NN * CC];

// ---------------------------------------------------------------------------
// FMA-only exp (avoids MUFU.EX2 throughput wall: 67M exps would cost ~500us on
// the MUFU pipe; this is ~8 FMA-class ops/element => ~16us chip-wide).
// exp(x) = 2^(x*log2e); integer/fraction split via magic constant, degree-5
// Taylor on f in [-0.5,0.5] (rel err ~2e-6), exponent spliced via bit add.
// Valid for x <= 0 (we always pass s - m <= 0); clamped at -87.
// ---------------------------------------------------------------------------
__device__ __forceinline__ float fast_exp(float x) {
    float y = fmaxf(x, -87.0f) * 1.4426950408889634f;
    float z = __fadd_rn(y, 12582912.0f);              // 1.5*2^23
    int   k = __float_as_int(z) - 0x4B400000;         // round(y)
    float f = __fsub_rn(y, __fsub_rn(z, 12582912.0f)); // y - round(y)
    float p =             1.33335581e-3f;
    p = fmaf(p, f, 9.61812910e-3f);
    p = fmaf(p, f, 5.55041087e-2f);
    p = fmaf(p, f, 2.40226507e-1f);
    p = fmaf(p, f, 6.93147181e-1f);
    p = fmaf(p, f, 1.0f);
    return __int_as_float(__float_as_int(p) + (k << 23));
}

// ---------------------------------------------------------------------------
// Kernel 1: fused QKV projection.
// out[b][i][o] = sum_c W[o][c] * X[b][c][i] + bias[o]   (i = spatial, o = chan)
// Writes channel-major-last layout so attention GEMMs read contiguous rows.
// grid: (NN/128, CC/128, B*3), 256 threads, 128x128 tile, 8x8 per thread.
// ---------------------------------------------------------------------------
__global__ __launch_bounds__(256) void proj_kernel(
    const float* __restrict__ x1, const float* __restrict__ x2,
    const float* __restrict__ Wq, const float* __restrict__ bq,
    const float* __restrict__ Wk, const float* __restrict__ bk,
    const float* __restrict__ Wv, const float* __restrict__ bv)
{
    int z = blockIdx.z;
    int b = z / 3, t = z % 3;
    const float* X    = (t == 0) ? x1 : x2;
    const float* W    = (t == 0) ? Wq : (t == 1) ? Wk : Wv;
    const float* bias = (t == 0) ? bq : (t == 1) ? bk : bv;
    float* dst        = (t == 0) ? g_q : (t == 1) ? g_k : g_v;
    X   += (size_t)b * CC * NN;
    dst += (size_t)b * NN * CC;

    int i0 = blockIdx.x * 128;
    int o0 = blockIdx.y * 128;

    __shared__ float As[8][128];   // [c][i]
    __shared__ float Bs[8][128];   // [c][o]

    int tid = threadIdx.x;
    int tx = tid & 15, ty = tid >> 4;

    int a_kk = tid >> 5;            // 0..7
    int a_i4 = (tid & 31) << 2;     // 0..124 step 4
    int b_o  = tid >> 1;            // 0..127
    int b_p  = (tid & 1) << 2;      // 0 or 4

    float acc[8][8];
#pragma unroll
    for (int i = 0; i < 8; i++)
#pragma unroll
        for (int j = 0; j < 8; j++) acc[i][j] = 0.0f;

    for (int c0 = 0; c0 < CC; c0 += 8) {
        float4 av = *(const float4*)(X + (size_t)(c0 + a_kk) * NN + i0 + a_i4);
        float4 wv = *(const float4*)(W + (size_t)(o0 + b_o) * CC + c0 + b_p);
        __syncthreads();
        *(float4*)(&As[a_kk][a_i4]) = av;
        Bs[b_p + 0][b_o] = wv.x;
        Bs[b_p + 1][b_o] = wv.y;
        Bs[b_p + 2][b_o] = wv.z;
        Bs[b_p + 3][b_o] = wv.w;
        __syncthreads();
#pragma unroll
        for (int kk = 0; kk < 8; kk++) {
            float a[8], bb[8];
            *(float4*)(a)      = *(const float4*)(&As[kk][ty * 8]);
            *(float4*)(a + 4)  = *(const float4*)(&As[kk][ty * 8 + 4]);
            *(float4*)(bb)     = *(const float4*)(&Bs[kk][tx * 8]);
            *(float4*)(bb + 4) = *(const float4*)(&Bs[kk][tx * 8 + 4]);
#pragma unroll
            for (int ii = 0; ii < 8; ii++)
#pragma unroll
                for (int oo = 0; oo < 8; oo++)
                    acc[ii][oo] = fmaf(a[ii], bb[oo], acc[ii][oo]);
        }
    }

    float bv8[8];
#pragma unroll
    for (int oo = 0; oo < 8; oo++) bv8[oo] = __ldg(bias + o0 + tx * 8 + oo);

#pragma unroll
    for (int ii = 0; ii < 8; ii++) {
        int i = i0 + ty * 8 + ii;
        float* drow = dst + (size_t)i * CC + o0 + tx * 8;
        float4 r0 = make_float4(acc[ii][0] + bv8[0], acc[ii][1] + bv8[1],
                                acc[ii][2] + bv8[2], acc[ii][3] + bv8[3]);
        float4 r1 = make_float4(acc[ii][4] + bv8[4], acc[ii][5] + bv8[5],
                                acc[ii][6] + bv8[6], acc[ii][7] + bv8[7]);
        *(float4*)(drow)     = r0;
        *(float4*)(drow + 4) = r1;
    }
}

// ---------------------------------------------------------------------------
// Kernel 2: scores S[b][i][j] = sum_c Q[b][i][c] * K[b][j][c]
// grid (32, 32, 4), 128x128 tile, K=256.
// ---------------------------------------------------------------------------
__global__ __launch_bounds__(256) void scores_kernel()
{
    int b = blockIdx.z;
    const float* Q = g_q + (size_t)b * NN * CC;
    const float* K = g_k + (size_t)b * NN * CC;
    float* S       = g_s + (size_t)b * NN * NN;

    int i0 = blockIdx.x * 128;
    int j0 = blockIdx.y * 128;

    __shared__ float As[8][128];   // [c][i]
    __shared__ float Bs[8][128];   // [c][j]

    int tid = threadIdx.x;
    int tx = tid & 15, ty = tid >> 4;
    int r = tid >> 1;              // 0..127
    int p = (tid & 1) << 2;        // 0 or 4

    float acc[8][8];
#pragma unroll
    for (int i = 0; i < 8; i++)
#pragma unroll
        for (int j = 0; j < 8; j++) acc[i][j] = 0.0f;

    for (int c0 = 0; c0 < CC; c0 += 8) {
        float4 qa = *(const float4*)(Q + (size_t)(i0 + r) * CC + c0 + p);
        float4 ka = *(const float4*)(K + (size_t)(j0 + r) * CC + c0 + p);
        __syncthreads();
        As[p + 0][r] = qa.x; As[p + 1][r] = qa.y;
        As[p + 2][r] = qa.z; As[p + 3][r] = qa.w;
        Bs[p + 0][r] = ka.x; Bs[p + 1][r] = ka.y;
        Bs[p + 2][r] = ka.z; Bs[p + 3][r] = ka.w;
        __syncthreads();
#pragma unroll
        for (int kk = 0; kk < 8; kk++) {
            float a[8], bb[8];
            *(float4*)(a)      = *(const float4*)(&As[kk][ty * 8]);
            *(float4*)(a + 4)  = *(const float4*)(&As[kk][ty * 8 + 4]);
            *(float4*)(bb)     = *(const float4*)(&Bs[kk][tx * 8]);
            *(float4*)(bb + 4) = *(const float4*)(&Bs[kk][tx * 8 + 4]);
#pragma unroll
            for (int ii = 0; ii < 8; ii++)
#pragma unroll
                for (int jj = 0; jj < 8; jj++)
                    acc[ii][jj] = fmaf(a[ii], bb[jj], acc[ii][jj]);
        }
    }

#pragma unroll
    for (int ii = 0; ii < 8; ii++) {
        float* srow = S + (size_t)(i0 + ty * 8 + ii) * NN + j0 + tx * 8;
        *(float4*)(srow)     = make_float4(acc[ii][0], acc[ii][1], acc[ii][2], acc[ii][3]);
        *(float4*)(srow + 4) = make_float4(acc[ii][4], acc[ii][5], acc[ii][6], acc[ii][7]);
    }
}

// ---------------------------------------------------------------------------
// Kernel 3: per-row softmax stats (max, 1/sum_exp). One 256-thread block per
// row; the whole 16KB row lives in registers (16 floats/thread).
// grid (NN, BB).
// ---------------------------------------------------------------------------
__global__ __launch_bounds__(256) void stats_kernel()
{
    int i = blockIdx.x;
    int b = blockIdx.y;
    const float4* row = (const float4*)(g_s + ((size_t)b * NN + i) * NN);
    int tid = threadIdx.x;

    float4 v[4];
#pragma unroll
    for (int u = 0; u < 4; u++) v[u] = row[tid + u * 256];

    float m = -1e30f;
#pragma unroll
    for (int u = 0; u < 4; u++) {
        m = fmaxf(m, fmaxf(fmaxf(v[u].x, v[u].y), fmaxf(v[u].z, v[u].w)));
    }

    __shared__ float red[8];
    __shared__ float bm, bl;
#pragma unroll
    for (int s = 16; s > 0; s >>= 1) m = fmaxf(m, __shfl_xor_sync(0xffffffffu, m, s));
    if ((tid & 31) == 0) red[tid >> 5] = m;
    __syncthreads();
    if (tid == 0) {
        float mm = red[0];
#pragma unroll
        for (int w = 1; w < 8; w++) mm = fmaxf(mm, red[w]);
        bm = mm;
    }
    __syncthreads();
    m = bm;

    float s = 0.0f;
#pragma unroll
    for (int u = 0; u < 4; u++) {
        s += fast_exp(v[u].x - m) + fast_exp(v[u].y - m)
           + fast_exp(v[u].z - m) + fast_exp(v[u].w - m);
    }
#pragma unroll
    for (int sh = 16; sh > 0; sh >>= 1) s += __shfl_xor_sync(0xffffffffu, s, sh);
    __syncthreads();
    if ((tid & 31) == 0) red[tid >> 5] = s;
    __syncthreads();
    if (tid == 0) {
        float ss = 0.0f;
#pragma unroll
        for (int w = 0; w < 8; w++) ss += red[w];
        bl = ss;
        g_m[b * NN + i]  = m;
        g_li[b * NN + i] = 1.0f / ss;
    }
}

// ---------------------------------------------------------------------------
// Kernel 4: O[b][i][c] = sum_j softmax(S)[i][j] * V[b][j][c]
// exp applied on-the-fly at the A-tile load (fast_exp, FMA-only).
// grid (32, 2, 4), 128x128 tile, K = 4096.
// ---------------------------------------------------------------------------
__global__ __launch_bounds__(256) void pv_kernel()
{
    int b = blockIdx.z;
    int i0 = blockIdx.x * 128;
    int c0 = blockIdx.y * 128;
    const float* S = g_s + (size_t)b * NN * NN;
    const float* V = g_v + (size_t)b * NN * CC;

    __shared__ float As[8][128];   // [j][i]  (P tile)
    __shared__ float Bs[8][128];   // [j][c]
    __shared__ float m_s[128], li_s[128];

    int tid = threadIdx.x;
    int tx = tid & 15, ty = tid >> 4;
    int r = tid >> 1;            // 0..127 (i within tile)
    int p = (tid & 1) << 2;      // 0 or 4 (j part)
    int b_kk = tid >> 5;         // 0..7
    int b_c4 = (tid & 31) << 2;  // 0..124

    if (tid < 128) {
        m_s[tid]  = g_m[b * NN + i0 + tid];
        li_s[tid] = g_li[b * NN + i0 + tid];
    }

    float acc[8][8];
#pragma unroll
    for (int i = 0; i < 8; i++)
#pragma unroll
        for (int j = 0; j < 8; j++) acc[i][j] = 0.0f;

    for (int j0 = 0; j0 < NN; j0 += 8) {
        float4 s4 = *(const float4*)(S + (size_t)(i0 + r) * NN + j0 + p);
        float4 v4 = *(const float4*)(V + (size_t)(j0 + b_kk) * CC + c0 + b_c4);
        __syncthreads();
        float mm = m_s[r];
        As[p + 0][r] = fast_exp(s4.x - mm);
        As[p + 1][r] = fast_exp(s4.y - mm);
        As[p + 2][r] = fast_exp(s4.z - mm);
        As[p + 3][r] = fast_exp(s4.w - mm);
        *(float4*)(&Bs[b_kk][b_c4]) = v4;
        __syncthreads();
#pragma unroll
        for (int kk = 0; kk < 8; kk++) {
            float a[8], bb[8];
            *(float4*)(a)      = *(const float4*)(&As[kk][ty * 8]);
            *(float4*)(a + 4)  = *(const float4*)(&As[kk][ty * 8 + 4]);
            *(float4*)(bb)     = *(const float4*)(&Bs[kk][tx * 8]);
            *(float4*)(bb + 4) = *(const float4*)(&Bs[kk][tx * 8 + 4]);
#pragma unroll
            for (int ii = 0; ii < 8; ii++)
#pragma unroll
                for (int cc = 0; cc < 8; cc++)
                    acc[ii][cc] = fmaf(a[ii], bb[cc], acc[ii][cc]);
        }
    }

#pragma unroll
    for (int ii = 0; ii < 8; ii++) {
        int i = i0 + ty * 8 + ii;
        float li = li_s[ty * 8 + ii];
        float* orow = g_o + ((size_t)b * NN + i) * CC + c0 + tx * 8;
        *(float4*)(orow)     = make_float4(acc[ii][0] * li, acc[ii][1] * li,
                                           acc[ii][2] * li, acc[ii][3] * li);
        *(float4*)(orow + 4) = make_float4(acc[ii][4] * li, acc[ii][5] * li,
                                           acc[ii][6] * li, acc[ii][7] * li);
    }
}

// ---------------------------------------------------------------------------
// Kernel 5: transpose O[b][i][c] -> out[b][c][h][w] (= out[b][c][i])
// grid (NN/32, CC/32, BB), block (32, 8), 32x32 smem tile.
// ---------------------------------------------------------------------------
__global__ void transpose_kernel(float* __restrict__ out)
{
    __shared__ float tile[32][33];
    int b  = blockIdx.z;
    int i0 = blockIdx.x * 32;
    int c0 = blockIdx.y * 32;
    int tx = threadIdx.x, ty = threadIdx.y;
    const float* src = g_o + (size_t)b * NN * CC;
    float* dst       = out + (size_t)b * CC * NN;
#pragma unroll
    for (int u = 0; u < 32; u += 8)
        tile[ty + u][tx] = src[(size_t)(i0 + ty + u) * CC + c0 + tx];
    __syncthreads();
#pragma unroll
    for (int u = 0; u < 32; u += 8)
        dst[(size_t)(c0 + ty + u) * NN + i0 + tx] = tile[tx][ty + u];
}

extern "C" void kernel_launch(void* const* d_in, const int* in_sizes, int n_in,
                              void* d_out, int out_size)
{
    const float* x1 = (const float*)d_in[0];
    const float* x2 = (const float*)d_in[1];
    const float* Wq = (const float*)d_in[2];
    const float* bq = (const float*)d_in[3];
    const float* Wk = (const float*)d_in[4];
    const float* bk = (const float*)d_in[5];
    const float* Wv = (const float*)d_in[6];
    const float* bv = (const float*)d_in[7];
    float* out = (float*)d_out;

    proj_kernel<<<dim3(NN / 128, CC / 128, BB * 3), 256>>>(x1, x2, Wq, bq, Wk, bk, Wv, bv);
    scores_kernel<<<dim3(NN / 128, NN / 128, BB), 256>>>();
    stats_kernel<<<dim3(NN, BB), 256>>>();
    pv_kernel<<<dim3(NN / 128, CC / 128, BB), 256>>>();
    transpose_kernel<<<dim3(NN / 32, CC / 32, BB), dim3(32, 8)>>>(out);
}

// round 3
// speedup vs baseline: 1.8054x; 1.8054x over previous
#include <cuda_runtime.h>
#include <cuda_bf16.h>
#include <cstdint>

#define BB 4
#define CC 256
#define NN 4096

// ---------------------------------------------------------------------------
// Scratch (allocation-free: __device__ bss)
// ---------------------------------------------------------------------------
__device__ __nv_bfloat16 g_qh[(size_t)BB * NN * CC];
__device__ __nv_bfloat16 g_ql[(size_t)BB * NN * CC];
__device__ __nv_bfloat16 g_kh[(size_t)BB * NN * CC];
__device__ __nv_bfloat16 g_kl[(size_t)BB * NN * CC];
__device__ float         g_v [(size_t)BB * NN * CC];   // V fp32 [b][i][c]
__device__ __nv_bfloat16 g_vth[(size_t)BB * CC * NN];  // V^T hi [b][c][j]
__device__ __nv_bfloat16 g_vtl[(size_t)BB * CC * NN];  // V^T lo
__device__ float g_s[(size_t)BB * NN * NN];            // scores fp32 (256 MB)
__device__ float g_m [BB * NN];
__device__ float g_li[BB * NN];

// ---------------------------------------------------------------------------
// PTX helpers (portable sm_80+ tensor path: mma.sync / ldmatrix / cp.async)
// ---------------------------------------------------------------------------
__device__ __forceinline__ uint32_t smem_u32(const void* p) {
    uint32_t a;
    asm("{ .reg .u64 t; cvta.to.shared.u64 t, %1; cvt.u32.u64 %0, t; }"
        : "=r"(a) : "l"(p));
    return a;
}

#define CP16(smem, gptr) \
    asm volatile("cp.async.ca.shared.global [%0], [%1], 16;" \
                 :: "r"(smem), "l"(gptr) : "memory")
#define CP_COMMIT() asm volatile("cp.async.commit_group;" ::: "memory")
#define CP_WAIT1()  asm volatile("cp.async.wait_group 1;" ::: "memory")
#define CP_WAIT0()  asm volatile("cp.async.wait_group 0;" ::: "memory")

#define LDSM4(r0, r1, r2, r3, addr) \
    asm volatile("ldmatrix.sync.aligned.m8n8.x4.shared.b16 {%0,%1,%2,%3}, [%4];" \
                 : "=r"(r0), "=r"(r1), "=r"(r2), "=r"(r3) : "r"(addr))

__device__ __forceinline__ void mma_bf16(float* d, const uint32_t* a,
                                         uint32_t b0, uint32_t b1) {
    asm volatile(
        "mma.sync.aligned.m16n8k16.row.col.f32.bf16.bf16.f32 "
        "{%0,%1,%2,%3}, {%4,%5,%6,%7}, {%8,%9}, {%0,%1,%2,%3};"
        : "+f"(d[0]), "+f"(d[1]), "+f"(d[2]), "+f"(d[3])
        : "r"(a[0]), "r"(a[1]), "r"(a[2]), "r"(a[3]), "r"(b0), "r"(b1));
}

// Tile geometry: CTA 128x128, k-chunk 32 bf16 (64B data padded to 80B rows:
// r*80 mod 128 hits all 8 16B-banks -> conflict-free ldmatrix).
#define TILE_B 10240          // 128 rows * 80B
#define STG_B  40960          // Ah | Al | Bh | Bl
#define DYN_SMEM 81920        // 2 stages

// ---------------------------------------------------------------------------
// FMA-only exp (valid for x<=0, clamped at -87); avoids MUFU.EX2 wall.
// ---------------------------------------------------------------------------
__device__ __forceinline__ float fast_exp(float x) {
    float y = fmaxf(x, -87.0f) * 1.4426950408889634f;
    float z = __fadd_rn(y, 12582912.0f);
    int   k = __float_as_int(z) - 0x4B400000;
    float f = __fsub_rn(y, __fsub_rn(z, 12582912.0f));
    float p =             1.33335581e-3f;
    p = fmaf(p, f, 9.61812910e-3f);
    p = fmaf(p, f, 5.55041087e-2f);
    p = fmaf(p, f, 2.40226507e-1f);
    p = fmaf(p, f, 6.93147181e-1f);
    p = fmaf(p, f, 1.0f);
    return __int_as_float(__float_as_int(p) + (k << 23));
}

__device__ __forceinline__ void bf16_split(float v, __nv_bfloat16& h, __nv_bfloat16& l) {
    h = __float2bfloat16_rn(v);
    l = __float2bfloat16_rn(v - __bfloat162float(h));
}

// ---------------------------------------------------------------------------
// Kernel 1: fused QKV projection (SIMT fp32 GEMM, 128x128 tiles).
// Q,K written as bf16 hi/lo [b][i][c]; V written fp32 [b][i][c].
// ---------------------------------------------------------------------------
__global__ __launch_bounds__(256) void proj_kernel(
    const float* __restrict__ x1, const float* __restrict__ x2,
    const float* __restrict__ Wq, const float* __restrict__ bq,
    const float* __restrict__ Wk, const float* __restrict__ bk,
    const float* __restrict__ Wv, const float* __restrict__ bv)
{
    int z = blockIdx.z;
    int b = z / 3, t = z % 3;
    const float* X    = (t == 0) ? x1 : x2;
    const float* W    = (t == 0) ? Wq : (t == 1) ? Wk : Wv;
    const float* bias = (t == 0) ? bq : (t == 1) ? bk : bv;
    X += (size_t)b * CC * NN;

    int i0 = blockIdx.x * 128;
    int o0 = blockIdx.y * 128;

    __shared__ float As[8][128];
    __shared__ float Bs[8][128];

    int tid = threadIdx.x;
    int tx = tid & 15, ty = tid >> 4;
    int a_kk = tid >> 5;
    int a_i4 = (tid & 31) << 2;
    int b_o  = tid >> 1;
    int b_p  = (tid & 1) << 2;

    float acc[8][8];
#pragma unroll
    for (int i = 0; i < 8; i++)
#pragma unroll
        for (int j = 0; j < 8; j++) acc[i][j] = 0.0f;

    for (int c0 = 0; c0 < CC; c0 += 8) {
        float4 av = *(const float4*)(X + (size_t)(c0 + a_kk) * NN + i0 + a_i4);
        float4 wv = *(const float4*)(W + (size_t)(o0 + b_o) * CC + c0 + b_p);
        __syncthreads();
        *(float4*)(&As[a_kk][a_i4]) = av;
        Bs[b_p + 0][b_o] = wv.x;
        Bs[b_p + 1][b_o] = wv.y;
        Bs[b_p + 2][b_o] = wv.z;
        Bs[b_p + 3][b_o] = wv.w;
        __syncthreads();
#pragma unroll
        for (int kk = 0; kk < 8; kk++) {
            float a[8], bb[8];
            *(float4*)(a)      = *(const float4*)(&As[kk][ty * 8]);
            *(float4*)(a + 4)  = *(const float4*)(&As[kk][ty * 8 + 4]);
            *(float4*)(bb)     = *(const float4*)(&Bs[kk][tx * 8]);
            *(float4*)(bb + 4) = *(const float4*)(&Bs[kk][tx * 8 + 4]);
#pragma unroll
            for (int ii = 0; ii < 8; ii++)
#pragma unroll
                for (int oo = 0; oo < 8; oo++)
                    acc[ii][oo] = fmaf(a[ii], bb[oo], acc[ii][oo]);
        }
    }

    float bv8[8];
#pragma unroll
    for (int oo = 0; oo < 8; oo++) bv8[oo] = __ldg(bias + o0 + tx * 8 + oo);

    if (t < 2) {
        __nv_bfloat16* dh = ((t == 0) ? g_qh : g_kh) + (size_t)b * NN * CC;
        __nv_bfloat16* dl = ((t == 0) ? g_ql : g_kl) + (size_t)b * NN * CC;
#pragma unroll
        for (int ii = 0; ii < 8; ii++) {
            int i = i0 + ty * 8 + ii;
            union { __nv_bfloat16 e[8]; uint4 v; } uh, ul;
#pragma unroll
            for (int oo = 0; oo < 8; oo++) {
                float val = acc[ii][oo] + bv8[oo];
                bf16_split(val, uh.e[oo], ul.e[oo]);
            }
            *(uint4*)(dh + (size_t)i * CC + o0 + tx * 8) = uh.v;
            *(uint4*)(dl + (size_t)i * CC + o0 + tx * 8) = ul.v;
        }
    } else {
        float* dst = g_v + (size_t)b * NN * CC;
#pragma unroll
        for (int ii = 0; ii < 8; ii++) {
            int i = i0 + ty * 8 + ii;
            float* drow = dst + (size_t)i * CC + o0 + tx * 8;
            *(float4*)(drow)     = make_float4(acc[ii][0] + bv8[0], acc[ii][1] + bv8[1],
                                               acc[ii][2] + bv8[2], acc[ii][3] + bv8[3]);
            *(float4*)(drow + 4) = make_float4(acc[ii][4] + bv8[4], acc[ii][5] + bv8[5],
                                               acc[ii][6] + bv8[6], acc[ii][7] + bv8[7]);
        }
    }
}

// ---------------------------------------------------------------------------
// Kernel 2: V transpose + bf16 split.  g_v[b][i][c] -> g_vth/g_vtl[b][c][j]
// ---------------------------------------------------------------------------
__global__ void vprep_kernel()
{
    __shared__ float tile[32][33];
    int b  = blockIdx.z;
    int i0 = blockIdx.x * 32;
    int c0 = blockIdx.y * 32;
    int tx = threadIdx.x, ty = threadIdx.y;
    const float* src = g_v + (size_t)b * NN * CC;
    __nv_bfloat16* dh = g_vth + (size_t)b * CC * NN;
    __nv_bfloat16* dl = g_vtl + (size_t)b * CC * NN;
#pragma unroll
    for (int u = 0; u < 32; u += 8)
        tile[ty + u][tx] = src[(size_t)(i0 + ty + u) * CC + c0 + tx];
    __syncthreads();
#pragma unroll
    for (int u = 0; u < 32; u += 8) {
        float v = tile[tx][ty + u];
        __nv_bfloat16 h, l;
        bf16_split(v, h, l);
        size_t idx = (size_t)(c0 + ty + u) * NN + i0 + tx;
        dh[idx] = h;
        dl[idx] = l;
    }
}

// ---------------------------------------------------------------------------
// Shared warp-MMA compute: one k32 stage, CTA 128x128, 8 warps (32x64 each).
// A/B in smem (hi/lo tiles), 3-term split, fp32 acc.
// ---------------------------------------------------------------------------
__device__ __forceinline__ void mma_stage(uint32_t st, uint32_t a_off, uint32_t b_off,
                                          float acc[2][8][4])
{
#pragma unroll
    for (int kk = 0; kk < 2; kk++) {
        uint32_t ah[2][4], al[2][4];
#pragma unroll
        for (int mi = 0; mi < 2; mi++) {
            uint32_t ad = st + a_off + mi * (16 * 80) + kk * 32;
            LDSM4(ah[mi][0], ah[mi][1], ah[mi][2], ah[mi][3], ad);
            LDSM4(al[mi][0], al[mi][1], al[mi][2], al[mi][3], ad + TILE_B);
        }
#pragma unroll
        for (int ng = 0; ng < 4; ng++) {
            uint32_t bd = st + b_off + ng * (16 * 80) + kk * 32;
            uint32_t bh[4], bl[4];
            LDSM4(bh[0], bh[1], bh[2], bh[3], bd);
            LDSM4(bl[0], bl[1], bl[2], bl[3], bd + TILE_B);
#pragma unroll
            for (int mi = 0; mi < 2; mi++) {
                mma_bf16(acc[mi][ng * 2],     ah[mi], bh[0], bh[1]);
                mma_bf16(acc[mi][ng * 2 + 1], ah[mi], bh[2], bh[3]);
                mma_bf16(acc[mi][ng * 2],     ah[mi], bl[0], bl[1]);
                mma_bf16(acc[mi][ng * 2 + 1], ah[mi], bl[2], bl[3]);
                mma_bf16(acc[mi][ng * 2],     al[mi], bh[0], bh[1]);
                mma_bf16(acc[mi][ng * 2 + 1], al[mi], bh[2], bh[3]);
            }
        }
    }
}

// ---------------------------------------------------------------------------
// Kernel 3: scores S = Q.K^T via mma.sync, 3-term bf16 split.
// grid (32, 32, 4), 256 threads.
// ---------------------------------------------------------------------------
__global__ void __launch_bounds__(256, 1) scores_mma()
{
    extern __shared__ char sm[];
    uint32_t sb = smem_u32(sm);
    int tid = threadIdx.x, wid = tid >> 5, lane = tid & 31;
    int b = blockIdx.z, i0 = blockIdx.x * 128, j0 = blockIdx.y * 128;
    int wm = wid & 3, wn = wid >> 2;

    const __nv_bfloat16* Qh = g_qh + (size_t)b * NN * CC;
    const __nv_bfloat16* Ql = g_ql + (size_t)b * NN * CC;
    const __nv_bfloat16* Kh = g_kh + (size_t)b * NN * CC;
    const __nv_bfloat16* Kl = g_kl + (size_t)b * NN * CC;
    float* S = g_s + (size_t)b * NN * NN;

    // loader mapping: thread -> (row, 32B half of the 64B row)
    int lrow = tid >> 1;
    int lc   = (tid & 1) * 32;
    const char* gq_h = (const char*)(Qh + (size_t)(i0 + lrow) * CC) + lc;
    const char* gq_l = (const char*)(Ql + (size_t)(i0 + lrow) * CC) + lc;
    const char* gk_h = (const char*)(Kh + (size_t)(j0 + lrow) * CC) + lc;
    const char* gk_l = (const char*)(Kl + (size_t)(j0 + lrow) * CC) + lc;
    uint32_t s_a = sb + lrow * 80 + lc;

    uint32_t a_off = (wm * 32 + (lane & 15)) * 80 + ((lane >> 4) << 4);
    uint32_t b_off = (wn * 64 + (lane & 7) + ((lane >> 4) << 3)) * 80
                   + (((lane >> 3) & 1) << 4) + 2 * TILE_B;

    float acc[2][8][4];
#pragma unroll
    for (int i = 0; i < 2; i++)
#pragma unroll
        for (int j = 0; j < 8; j++)
#pragma unroll
            for (int r = 0; r < 4; r++) acc[i][j][r] = 0.0f;

#define ISSUE_S(ch, stg) do {                                    \
        uint32_t d = s_a + (stg) * STG_B;                        \
        size_t go = (size_t)(ch) * 64;                           \
        CP16(d,                  gq_h + go);                     \
        CP16(d + 16,             gq_h + go + 16);                \
        CP16(d + TILE_B,         gq_l + go);                     \
        CP16(d + TILE_B + 16,    gq_l + go + 16);                \
        CP16(d + 2 * TILE_B,     gk_h + go);                     \
        CP16(d + 2 * TILE_B + 16, gk_h + go + 16);               \
        CP16(d + 3 * TILE_B,     gk_l + go);                     \
        CP16(d + 3 * TILE_B + 16, gk_l + go + 16);               \
        CP_COMMIT();                                             \
    } while (0)

    ISSUE_S(0, 0);
#pragma unroll 2
    for (int ch = 0; ch < 8; ch++) {
        int s = ch & 1;
        if (ch < 7) { ISSUE_S(ch + 1, s ^ 1); CP_WAIT1(); }
        else        { CP_WAIT0(); }
        __syncthreads();
        mma_stage(sb + s * STG_B, a_off, b_off, acc);
        __syncthreads();
    }
#undef ISSUE_S

#pragma unroll
    for (int mi = 0; mi < 2; mi++) {
        int row = i0 + wm * 32 + mi * 16 + (lane >> 2);
#pragma unroll
        for (int np = 0; np < 8; np++) {
            int col = j0 + wn * 64 + np * 8 + (lane & 3) * 2;
            *(float2*)(S + (size_t)row * NN + col) =
                make_float2(acc[mi][np][0], acc[mi][np][1]);
            *(float2*)(S + (size_t)(row + 8) * NN + col) =
                make_float2(acc[mi][np][2], acc[mi][np][3]);
        }
    }
}

// ---------------------------------------------------------------------------
// Kernel 4: per-row softmax stats (max, 1/sum_exp). grid (NN, BB), 256 thr.
// ---------------------------------------------------------------------------
__global__ __launch_bounds__(256) void stats_kernel()
{
    int i = blockIdx.x;
    int b = blockIdx.y;
    const float4* row = (const float4*)(g_s + ((size_t)b * NN + i) * NN);
    int tid = threadIdx.x;

    float4 v[4];
#pragma unroll
    for (int u = 0; u < 4; u++) v[u] = row[tid + u * 256];

    float m = -1e30f;
#pragma unroll
    for (int u = 0; u < 4; u++)
        m = fmaxf(m, fmaxf(fmaxf(v[u].x, v[u].y), fmaxf(v[u].z, v[u].w)));

    __shared__ float red[8];
    __shared__ float bm;
#pragma unroll
    for (int s = 16; s > 0; s >>= 1) m = fmaxf(m, __shfl_xor_sync(0xffffffffu, m, s));
    if ((tid & 31) == 0) red[tid >> 5] = m;
    __syncthreads();
    if (tid == 0) {
        float mm = red[0];
#pragma unroll
        for (int w = 1; w < 8; w++) mm = fmaxf(mm, red[w]);
        bm = mm;
    }
    __syncthreads();
    m = bm;

    float s = 0.0f;
#pragma unroll
    for (int u = 0; u < 4; u++)
        s += fast_exp(v[u].x - m) + fast_exp(v[u].y - m)
           + fast_exp(v[u].z - m) + fast_exp(v[u].w - m);
#pragma unroll
    for (int sh = 16; sh > 0; sh >>= 1) s += __shfl_xor_sync(0xffffffffu, s, sh);
    __syncthreads();
    if ((tid & 31) == 0) red[tid >> 5] = s;
    __syncthreads();
    if (tid == 0) {
        float ss = 0.0f;
#pragma unroll
        for (int w = 0; w < 8; w++) ss += red[w];
        g_m[b * NN + i]  = m;
        g_li[b * NN + i] = 1.0f / ss;
    }
}

// ---------------------------------------------------------------------------
// Kernel 5: PV via mma.sync.  O[i][c] = sum_j exp(S[i][j]-m) * Vt[c][j] / l.
// A tile (P) produced in-kernel (fast_exp + split), S prefetched in regs.
// Epilogue: scale by 1/l, smem transpose, write out[b][c][i] directly.
// grid (32, 2, 4), 256 threads.
// ---------------------------------------------------------------------------
__global__ void __launch_bounds__(256, 1) pv_mma(float* __restrict__ out)
{
    extern __shared__ char sm[];
    __shared__ float m_s[128], li_s[128];
    uint32_t sb = smem_u32(sm);
    int tid = threadIdx.x, wid = tid >> 5, lane = tid & 31;
    int b = blockIdx.z, i0 = blockIdx.x * 128, c0 = blockIdx.y * 128;
    int wm = wid & 3, wn = wid >> 2;

    const float* S = g_s + (size_t)b * NN * NN;
    const __nv_bfloat16* Vh = g_vth + (size_t)b * CC * NN;
    const __nv_bfloat16* Vl = g_vtl + (size_t)b * CC * NN;

    if (tid < 128) {
        m_s[tid]  = g_m[b * NN + i0 + tid];
        li_s[tid] = g_li[b * NN + i0 + tid];
    }

    // A producer mapping: thread -> (row, 16-col half)
    int arow = tid & 127, ahalf = tid >> 7;
    const float* gS = S + (size_t)(i0 + arow) * NN + ahalf * 16;
    uint32_t s_aw = sb + arow * 80 + ahalf * 32;

    // B loader mapping
    int lrow = tid >> 1;
    int lc   = (tid & 1) * 32;
    const char* gv_h = (const char*)(Vh + (size_t)(c0 + lrow) * NN) + lc;
    const char* gv_l = (const char*)(Vl + (size_t)(c0 + lrow) * NN) + lc;
    uint32_t s_b = sb + lrow * 80 + lc + 2 * TILE_B;

    uint32_t a_off = (wm * 32 + (lane & 15)) * 80 + ((lane >> 4) << 4);
    uint32_t b_off = (wn * 64 + (lane & 7) + ((lane >> 4) << 3)) * 80
                   + (((lane >> 3) & 1) << 4) + 2 * TILE_B;

    float acc[2][8][4];
#pragma unroll
    for (int i = 0; i < 2; i++)
#pragma unroll
        for (int j = 0; j < 8; j++)
#pragma unroll
            for (int r = 0; r < 4; r++) acc[i][j][r] = 0.0f;

#define ISSUE_B(ch, stg) do {                                    \
        uint32_t d = s_b + (stg) * STG_B;                        \
        size_t go = (size_t)(ch) * 64;                           \
        CP16(d,                  gv_h + go);                     \
        CP16(d + 16,             gv_h + go + 16);                \
        CP16(d + TILE_B,         gv_l + go);                     \
        CP16(d + TILE_B + 16,    gv_l + go + 16);                \
        CP_COMMIT();                                             \
    } while (0)

    float4 sv[4];
    {
        const float4* p = (const float4*)(gS);
#pragma unroll
        for (int u = 0; u < 4; u++) sv[u] = p[u];
    }
    ISSUE_B(0, 0);

    for (int ch = 0; ch < 128; ch++) {
        int s = ch & 1;
        __syncthreads();   // stage s fully consumed (compute ch-2 done)
        // write A tile (P hi/lo) for chunk ch from prefetched sv
        {
            float mrow = m_s[arow];
            union { __nv_bfloat16 e[16]; uint4 v[2]; } uh, ul;
#pragma unroll
            for (int u = 0; u < 4; u++) {
                float e0 = fast_exp(sv[u].x - mrow);
                float e1 = fast_exp(sv[u].y - mrow);
                float e2 = fast_exp(sv[u].z - mrow);
                float e3 = fast_exp(sv[u].w - mrow);
                bf16_split(e0, uh.e[u * 4 + 0], ul.e[u * 4 + 0]);
                bf16_split(e1, uh.e[u * 4 + 1], ul.e[u * 4 + 1]);
                bf16_split(e2, uh.e[u * 4 + 2], ul.e[u * 4 + 2]);
                bf16_split(e3, uh.e[u * 4 + 3], ul.e[u * 4 + 3]);
            }
            uint32_t d = s_aw + s * STG_B;
            *(uint4*)(sm + (d - sb))          = uh.v[0];
            *(uint4*)(sm + (d - sb) + 16)     = uh.v[1];
            *(uint4*)(sm + (d - sb) + TILE_B)      = ul.v[0];
            *(uint4*)(sm + (d - sb) + TILE_B + 16) = ul.v[1];
        }
        if (ch < 127) {
            ISSUE_B(ch + 1, s ^ 1);
            const float4* p = (const float4*)(gS + (ch + 1) * 32);
#pragma unroll
            for (int u = 0; u < 4; u++) sv[u] = p[u];
            CP_WAIT1();
        } else {
            CP_WAIT0();
        }
        __syncthreads();   // A visible + B(ch) landed
        mma_stage(sb + s * STG_B, a_off, b_off, acc);
    }
#undef ISSUE_B

    // Epilogue: scale by 1/l, transpose via smem, write out[b][c][i]
    __syncthreads();
    float* smt = (float*)sm;   // 128 x 132 fp32
#pragma unroll
    for (int mi = 0; mi < 2; mi++) {
        int r0 = wm * 32 + mi * 16 + (lane >> 2);
        float l0 = li_s[r0], l1 = li_s[r0 + 8];
#pragma unroll
        for (int np = 0; np < 8; np++) {
            int c = wn * 64 + np * 8 + (lane & 3) * 2;
            smt[(c + 0) * 132 + r0]     = acc[mi][np][0] * l0;
            smt[(c + 1) * 132 + r0]     = acc[mi][np][1] * l0;
            smt[(c + 0) * 132 + r0 + 8] = acc[mi][np][2] * l1;
            smt[(c + 1) * 132 + r0 + 8] = acc[mi][np][3] * l1;
        }
    }
    __syncthreads();
    {
        int cc = tid >> 1, half = tid & 1;
        float* op = out + ((size_t)b * CC + c0 + cc) * NN + i0 + half * 64;
        const float* sp = smt + cc * 132 + half * 64;
#pragma unroll
        for (int u = 0; u < 16; u++)
            ((float4*)op)[u] = ((const float4*)sp)[u];
    }
}

extern "C" void kernel_launch(void* const* d_in, const int* in_sizes, int n_in,
                              void* d_out, int out_size)
{
    const float* x1 = (const float*)d_in[0];
    const float* x2 = (const float*)d_in[1];
    const float* Wq = (const float*)d_in[2];
    const float* bq = (const float*)d_in[3];
    const float* Wk = (const float*)d_in[4];
    const float* bk = (const float*)d_in[5];
    const float* Wv = (const float*)d_in[6];
    const float* bv = (const float*)d_in[7];
    float* out = (float*)d_out;

    cudaFuncSetAttribute(scores_mma, cudaFuncAttributeMaxDynamicSharedMemorySize, DYN_SMEM);
    cudaFuncSetAttribute(pv_mma,     cudaFuncAttributeMaxDynamicSharedMemorySize, DYN_SMEM);

    proj_kernel<<<dim3(NN / 128, CC / 128, BB * 3), 256>>>(x1, x2, Wq, bq, Wk, bk, Wv, bv);
    vprep_kernel<<<dim3(NN / 32, CC / 32, BB), dim3(32, 8)>>>();
    scores_mma<<<dim3(NN / 128, NN / 128, BB), 256, DYN_SMEM>>>();
    stats_kernel<<<dim3(NN, BB), 256>>>();
    pv_mma<<<dim3(NN / 128, CC / 128, BB), 256, DYN_SMEM>>>(out);
}

// round 4
// speedup vs baseline: 2.1979x; 1.2174x over previous
#include <cuda_runtime.h>
#include <cuda_bf16.h>
#include <cstdint>

#define BB 4
#define CC 256
#define NN 4096

// ---------------------------------------------------------------------------
// Scratch (allocation-free: __device__ bss)
// ---------------------------------------------------------------------------
__device__ __nv_bfloat16 g_qh[(size_t)BB * NN * CC];
__device__ __nv_bfloat16 g_ql[(size_t)BB * NN * CC];
__device__ __nv_bfloat16 g_kh[(size_t)BB * NN * CC];
__device__ __nv_bfloat16 g_kl[(size_t)BB * NN * CC];
__device__ float         g_v [(size_t)BB * NN * CC];   // V fp32 [b][i][c]
__device__ __nv_bfloat16 g_vth[(size_t)BB * CC * NN];  // V^T hi [b][c][j]
__device__ __nv_bfloat16 g_vtl[(size_t)BB * CC * NN];  // V^T lo
__device__ float g_s[(size_t)BB * NN * NN];            // scores fp32 (256 MB)
__device__ float g_pm[(size_t)BB * NN * 32];           // partial row max per j-tile
__device__ float g_pl[(size_t)BB * NN * 32];           // partial sumexp per j-tile
__device__ float g_m [BB * NN];
__device__ float g_li[BB * NN];

// ---------------------------------------------------------------------------
// PTX helpers (portable sm_80+ tensor path: mma.sync / ldmatrix / cp.async)
// ---------------------------------------------------------------------------
__device__ __forceinline__ uint32_t smem_u32(const void* p) {
    uint32_t a;
    asm("{ .reg .u64 t; cvta.to.shared.u64 t, %1; cvt.u32.u64 %0, t; }"
        : "=r"(a) : "l"(p));
    return a;
}

#define CP16(smem, gptr) \
    asm volatile("cp.async.ca.shared.global [%0], [%1], 16;" \
                 :: "r"(smem), "l"(gptr) : "memory")
#define CP_COMMIT() asm volatile("cp.async.commit_group;" ::: "memory")
#define CP_WAIT1()  asm volatile("cp.async.wait_group 1;" ::: "memory")
#define CP_WAIT0()  asm volatile("cp.async.wait_group 0;" ::: "memory")

#define LDSM4(r0, r1, r2, r3, addr) \
    asm volatile("ldmatrix.sync.aligned.m8n8.x4.shared.b16 {%0,%1,%2,%3}, [%4];" \
                 : "=r"(r0), "=r"(r1), "=r"(r2), "=r"(r3) : "r"(addr))

__device__ __forceinline__ void mma_bf16(float* d, const uint32_t* a,
                                         uint32_t b0, uint32_t b1) {
    asm volatile(
        "mma.sync.aligned.m16n8k16.row.col.f32.bf16.bf16.f32 "
        "{%0,%1,%2,%3}, {%4,%5,%6,%7}, {%8,%9}, {%0,%1,%2,%3};"
        : "+f"(d[0]), "+f"(d[1]), "+f"(d[2]), "+f"(d[3])
        : "r"(a[0]), "r"(a[1]), "r"(a[2]), "r"(a[3]), "r"(b0), "r"(b1));
}

// k-chunk 32 bf16 per 128-row tile: 64B data padded to 80B rows
// (r*80 mod 128 covers all 8 16B banks -> conflict-free ldmatrix).
#define TILE_B 10240          // 128 rows * 80B
#define STG_B  40960          // scores stage: Ah | Al | Bh | Bl (128-row B)
#define SC_SMEM  (2 * STG_B)  // 81920 (2 CTAs/SM fit)

// pv stage: Ah(10240) | Al(10240) | Bh(20480, 256 rows) | Bl(20480)
#define PV_AL  10240
#define PV_BH  20480
#define PV_BL  40960
#define PV_STG 61440
#define PV_SMEM (2 * PV_STG)  // 122880

// ---------------------------------------------------------------------------
// FMA-only exp (valid for x<=0, clamped at -87); avoids MUFU.EX2 wall.
// ---------------------------------------------------------------------------
__device__ __forceinline__ float fast_exp(float x) {
    float y = fmaxf(x, -87.0f) * 1.4426950408889634f;
    float z = __fadd_rn(y, 12582912.0f);
    int   k = __float_as_int(z) - 0x4B400000;
    float f = __fsub_rn(y, __fsub_rn(z, 12582912.0f));
    float p =             1.33335581e-3f;
    p = fmaf(p, f, 9.61812910e-3f);
    p = fmaf(p, f, 5.55041087e-2f);
    p = fmaf(p, f, 2.40226507e-1f);
    p = fmaf(p, f, 6.93147181e-1f);
    p = fmaf(p, f, 1.0f);
    return __int_as_float(__float_as_int(p) + (k << 23));
}

__device__ __forceinline__ void bf16_split(float v, __nv_bfloat16& h, __nv_bfloat16& l) {
    h = __float2bfloat16_rn(v);
    l = __float2bfloat16_rn(v - __bfloat162float(h));
}

// ---------------------------------------------------------------------------
// Kernel 1: fused QKV projection (SIMT fp32 GEMM, 128x128 tiles).
// ---------------------------------------------------------------------------
__global__ __launch_bounds__(256) void proj_kernel(
    const float* __restrict__ x1, const float* __restrict__ x2,
    const float* __restrict__ Wq, const float* __restrict__ bq,
    const float* __restrict__ Wk, const float* __restrict__ bk,
    const float* __restrict__ Wv, const float* __restrict__ bv)
{
    int z = blockIdx.z;
    int b = z / 3, t = z % 3;
    const float* X    = (t == 0) ? x1 : x2;
    const float* W    = (t == 0) ? Wq : (t == 1) ? Wk : Wv;
    const float* bias = (t == 0) ? bq : (t == 1) ? bk : bv;
    X += (size_t)b * CC * NN;

    int i0 = blockIdx.x * 128;
    int o0 = blockIdx.y * 128;

    __shared__ float As[8][128];
    __shared__ float Bs[8][128];

    int tid = threadIdx.x;
    int tx = tid & 15, ty = tid >> 4;
    int a_kk = tid >> 5;
    int a_i4 = (tid & 31) << 2;
    int b_o  = tid >> 1;
    int b_p  = (tid & 1) << 2;

    float acc[8][8];
#pragma unroll
    for (int i = 0; i < 8; i++)
#pragma unroll
        for (int j = 0; j < 8; j++) acc[i][j] = 0.0f;

    for (int c0 = 0; c0 < CC; c0 += 8) {
        float4 av = *(const float4*)(X + (size_t)(c0 + a_kk) * NN + i0 + a_i4);
        float4 wv = *(const float4*)(W + (size_t)(o0 + b_o) * CC + c0 + b_p);
        __syncthreads();
        *(float4*)(&As[a_kk][a_i4]) = av;
        Bs[b_p + 0][b_o] = wv.x;
        Bs[b_p + 1][b_o] = wv.y;
        Bs[b_p + 2][b_o] = wv.z;
        Bs[b_p + 3][b_o] = wv.w;
        __syncthreads();
#pragma unroll
        for (int kk = 0; kk < 8; kk++) {
            float a[8], bb[8];
            *(float4*)(a)      = *(const float4*)(&As[kk][ty * 8]);
            *(float4*)(a + 4)  = *(const float4*)(&As[kk][ty * 8 + 4]);
            *(float4*)(bb)     = *(const float4*)(&Bs[kk][tx * 8]);
            *(float4*)(bb + 4) = *(const float4*)(&Bs[kk][tx * 8 + 4]);
#pragma unroll
            for (int ii = 0; ii < 8; ii++)
#pragma unroll
                for (int oo = 0; oo < 8; oo++)
                    acc[ii][oo] = fmaf(a[ii], bb[oo], acc[ii][oo]);
        }
    }

    float bv8[8];
#pragma unroll
    for (int oo = 0; oo < 8; oo++) bv8[oo] = __ldg(bias + o0 + tx * 8 + oo);

    if (t < 2) {
        __nv_bfloat16* dh = ((t == 0) ? g_qh : g_kh) + (size_t)b * NN * CC;
        __nv_bfloat16* dl = ((t == 0) ? g_ql : g_kl) + (size_t)b * NN * CC;
#pragma unroll
        for (int ii = 0; ii < 8; ii++) {
            int i = i0 + ty * 8 + ii;
            union { __nv_bfloat16 e[8]; uint4 v; } uh, ul;
#pragma unroll
            for (int oo = 0; oo < 8; oo++) {
                float val = acc[ii][oo] + bv8[oo];
                bf16_split(val, uh.e[oo], ul.e[oo]);
            }
            *(uint4*)(dh + (size_t)i * CC + o0 + tx * 8) = uh.v;
            *(uint4*)(dl + (size_t)i * CC + o0 + tx * 8) = ul.v;
        }
    } else {
        float* dst = g_v + (size_t)b * NN * CC;
#pragma unroll
        for (int ii = 0; ii < 8; ii++) {
            int i = i0 + ty * 8 + ii;
            float* drow = dst + (size_t)i * CC + o0 + tx * 8;
            *(float4*)(drow)     = make_float4(acc[ii][0] + bv8[0], acc[ii][1] + bv8[1],
                                               acc[ii][2] + bv8[2], acc[ii][3] + bv8[3]);
            *(float4*)(drow + 4) = make_float4(acc[ii][4] + bv8[4], acc[ii][5] + bv8[5],
                                               acc[ii][6] + bv8[6], acc[ii][7] + bv8[7]);
        }
    }
}

// ---------------------------------------------------------------------------
// Kernel 2: V transpose + bf16 split.  g_v[b][i][c] -> g_vth/g_vtl[b][c][j]
// ---------------------------------------------------------------------------
__global__ void vprep_kernel()
{
    __shared__ float tile[32][33];
    int b  = blockIdx.z;
    int i0 = blockIdx.x * 32;
    int c0 = blockIdx.y * 32;
    int tx = threadIdx.x, ty = threadIdx.y;
    const float* src = g_v + (size_t)b * NN * CC;
    __nv_bfloat16* dh = g_vth + (size_t)b * CC * NN;
    __nv_bfloat16* dl = g_vtl + (size_t)b * CC * NN;
#pragma unroll
    for (int u = 0; u < 32; u += 8)
        tile[ty + u][tx] = src[(size_t)(i0 + ty + u) * CC + c0 + tx];
    __syncthreads();
#pragma unroll
    for (int u = 0; u < 32; u += 8) {
        float v = tile[tx][ty + u];
        __nv_bfloat16 h, l;
        bf16_split(v, h, l);
        size_t idx = (size_t)(c0 + ty + u) * NN + i0 + tx;
        dh[idx] = h;
        dl[idx] = l;
    }
}

// ---------------------------------------------------------------------------
// Warp MMA for one k32 stage: warp tile 32 x 64, 3-term split.
// a_lo_d / b_lo_d = byte delta from hi tile to lo tile.
// ---------------------------------------------------------------------------
__device__ __forceinline__ void mma_stage(uint32_t st, uint32_t a_off, uint32_t b_off,
                                          uint32_t a_lo_d, uint32_t b_lo_d,
                                          float acc[2][8][4])
{
#pragma unroll
    for (int kk = 0; kk < 2; kk++) {
        uint32_t ah[2][4], al[2][4];
#pragma unroll
        for (int mi = 0; mi < 2; mi++) {
            uint32_t ad = st + a_off + mi * (16 * 80) + kk * 32;
            LDSM4(ah[mi][0], ah[mi][1], ah[mi][2], ah[mi][3], ad);
            LDSM4(al[mi][0], al[mi][1], al[mi][2], al[mi][3], ad + a_lo_d);
        }
#pragma unroll
        for (int ng = 0; ng < 4; ng++) {
            uint32_t bd = st + b_off + ng * (16 * 80) + kk * 32;
            uint32_t bh[4], bl[4];
            LDSM4(bh[0], bh[1], bh[2], bh[3], bd);
            LDSM4(bl[0], bl[1], bl[2], bl[3], bd + b_lo_d);
#pragma unroll
            for (int mi = 0; mi < 2; mi++) {
                mma_bf16(acc[mi][ng * 2],     ah[mi], bh[0], bh[1]);
                mma_bf16(acc[mi][ng * 2 + 1], ah[mi], bh[2], bh[3]);
                mma_bf16(acc[mi][ng * 2],     ah[mi], bl[0], bl[1]);
                mma_bf16(acc[mi][ng * 2 + 1], ah[mi], bl[2], bl[3]);
                mma_bf16(acc[mi][ng * 2],     al[mi], bh[0], bh[1]);
                mma_bf16(acc[mi][ng * 2 + 1], al[mi], bh[2], bh[3]);
            }
        }
    }
}

// ---------------------------------------------------------------------------
// Kernel 3: scores S = Q.K^T via mma.sync + fused partial softmax stats.
// grid (32, 32, 4), 256 threads, 2 CTAs/SM.
// ---------------------------------------------------------------------------
__global__ void __launch_bounds__(256, 2) scores_mma()
{
    extern __shared__ char sm[];
    __shared__ float pm[128][2], pl[128][2];
    uint32_t sb = smem_u32(sm);
    int tid = threadIdx.x, wid = tid >> 5, lane = tid & 31;
    int b = blockIdx.z, i0 = blockIdx.x * 128, j0 = blockIdx.y * 128;
    int wm = wid & 3, wn = wid >> 2;

    const __nv_bfloat16* Qh = g_qh + (size_t)b * NN * CC;
    const __nv_bfloat16* Ql = g_ql + (size_t)b * NN * CC;
    const __nv_bfloat16* Kh = g_kh + (size_t)b * NN * CC;
    const __nv_bfloat16* Kl = g_kl + (size_t)b * NN * CC;
    float* S = g_s + (size_t)b * NN * NN;

    int lrow = tid >> 1;
    int lc   = (tid & 1) * 32;
    const char* gq_h = (const char*)(Qh + (size_t)(i0 + lrow) * CC) + lc;
    const char* gq_l = (const char*)(Ql + (size_t)(i0 + lrow) * CC) + lc;
    const char* gk_h = (const char*)(Kh + (size_t)(j0 + lrow) * CC) + lc;
    const char* gk_l = (const char*)(Kl + (size_t)(j0 + lrow) * CC) + lc;
    uint32_t s_a = sb + lrow * 80 + lc;

    uint32_t a_off = (wm * 32 + (lane & 15)) * 80 + ((lane >> 4) << 4);
    uint32_t b_off = (wn * 64 + (lane & 7) + ((lane >> 4) << 3)) * 80
                   + (((lane >> 3) & 1) << 4) + 2 * TILE_B;

    float acc[2][8][4];
#pragma unroll
    for (int i = 0; i < 2; i++)
#pragma unroll
        for (int j = 0; j < 8; j++)
#pragma unroll
            for (int r = 0; r < 4; r++) acc[i][j][r] = 0.0f;

#define ISSUE_S(ch, stg) do {                                    \
        uint32_t d = s_a + (stg) * STG_B;                        \
        size_t go = (size_t)(ch) * 64;                           \
        CP16(d,                   gq_h + go);                    \
        CP16(d + 16,              gq_h + go + 16);               \
        CP16(d + TILE_B,          gq_l + go);                    \
        CP16(d + TILE_B + 16,     gq_l + go + 16);               \
        CP16(d + 2 * TILE_B,      gk_h + go);                    \
        CP16(d + 2 * TILE_B + 16, gk_h + go + 16);               \
        CP16(d + 3 * TILE_B,      gk_l + go);                    \
        CP16(d + 3 * TILE_B + 16, gk_l + go + 16);               \
        CP_COMMIT();                                             \
    } while (0)

    ISSUE_S(0, 0);
#pragma unroll 2
    for (int ch = 0; ch < 8; ch++) {
        int s = ch & 1;
        if (ch < 7) { ISSUE_S(ch + 1, s ^ 1); CP_WAIT1(); }
        else        { CP_WAIT0(); }
        __syncthreads();
        mma_stage(sb + s * STG_B, a_off, b_off, TILE_B, TILE_B, acc);
        __syncthreads();
    }
#undef ISSUE_S

    // Store S tile
#pragma unroll
    for (int mi = 0; mi < 2; mi++) {
        int row = i0 + wm * 32 + mi * 16 + (lane >> 2);
#pragma unroll
        for (int np = 0; np < 8; np++) {
            int col = j0 + wn * 64 + np * 8 + (lane & 3) * 2;
            *(float2*)(S + (size_t)row * NN + col) =
                make_float2(acc[mi][np][0], acc[mi][np][1]);
            *(float2*)(S + (size_t)(row + 8) * NN + col) =
                make_float2(acc[mi][np][2], acc[mi][np][3]);
        }
    }

    // Fused partial softmax stats over this 128-col tile (from registers).
    int q = lane >> 2, qt = lane & 3;
    float mloc[2][2];
#pragma unroll
    for (int mi = 0; mi < 2; mi++)
#pragma unroll
        for (int rh = 0; rh < 2; rh++) {
            float m = -1e30f;
#pragma unroll
            for (int np = 0; np < 8; np++)
                m = fmaxf(m, fmaxf(acc[mi][np][rh * 2], acc[mi][np][rh * 2 + 1]));
            mloc[mi][rh] = m;
        }
#pragma unroll
    for (int d = 1; d <= 2; d <<= 1) {
#pragma unroll
        for (int mi = 0; mi < 2; mi++)
#pragma unroll
            for (int rh = 0; rh < 2; rh++)
                mloc[mi][rh] = fmaxf(mloc[mi][rh],
                                     __shfl_xor_sync(0xffffffffu, mloc[mi][rh], d));
    }
    if (qt == 0) {
#pragma unroll
        for (int mi = 0; mi < 2; mi++)
#pragma unroll
            for (int rh = 0; rh < 2; rh++)
                pm[wm * 32 + mi * 16 + rh * 8 + q][wn] = mloc[mi][rh];
    }
    __syncthreads();
    float mrow[2][2], srow[2][2];
#pragma unroll
    for (int mi = 0; mi < 2; mi++)
#pragma unroll
        for (int rh = 0; rh < 2; rh++) {
            int row = wm * 32 + mi * 16 + rh * 8 + q;
            float m = fmaxf(pm[row][0], pm[row][1]);
            mrow[mi][rh] = m;
            float s = 0.0f;
#pragma unroll
            for (int np = 0; np < 8; np++)
                s += fast_exp(acc[mi][np][rh * 2] - m)
                   + fast_exp(acc[mi][np][rh * 2 + 1] - m);
            srow[mi][rh] = s;
        }
#pragma unroll
    for (int d = 1; d <= 2; d <<= 1) {
#pragma unroll
        for (int mi = 0; mi < 2; mi++)
#pragma unroll
            for (int rh = 0; rh < 2; rh++)
                srow[mi][rh] += __shfl_xor_sync(0xffffffffu, srow[mi][rh], d);
    }
    if (qt == 0) {
#pragma unroll
        for (int mi = 0; mi < 2; mi++)
#pragma unroll
            for (int rh = 0; rh < 2; rh++)
                pl[wm * 32 + mi * 16 + rh * 8 + q][wn] = srow[mi][rh];
    }
    __syncthreads();
    if (qt == 0 && wn == 0) {
#pragma unroll
        for (int mi = 0; mi < 2; mi++)
#pragma unroll
            for (int rh = 0; rh < 2; rh++) {
                int row = wm * 32 + mi * 16 + rh * 8 + q;
                size_t idx = ((size_t)b * NN + i0 + row) * 32 + blockIdx.y;
                g_pm[idx] = mrow[mi][rh];
                g_pl[idx] = pl[row][0] + pl[row][1];
            }
    }
}

// ---------------------------------------------------------------------------
// Kernel 4: merge partial stats. One warp per row (32 partials).
// grid (BB*NN/8), 256 threads.
// ---------------------------------------------------------------------------
__global__ __launch_bounds__(256) void merge_kernel()
{
    int row  = blockIdx.x * 8 + (threadIdx.x >> 5);
    int lane = threadIdx.x & 31;
    float m_t = g_pm[(size_t)row * 32 + lane];
    float l_t = g_pl[(size_t)row * 32 + lane];
    float m = m_t;
#pragma unroll
    for (int d = 16; d > 0; d >>= 1) m = fmaxf(m, __shfl_xor_sync(0xffffffffu, m, d));
    float l = l_t * fast_exp(m_t - m);
#pragma unroll
    for (int d = 16; d > 0; d >>= 1) l += __shfl_xor_sync(0xffffffffu, l, d);
    if (lane == 0) { g_m[row] = m; g_li[row] = 1.0f / l; }
}

// ---------------------------------------------------------------------------
// Kernel 5: PV via mma.sync, N=256 per CTA, 512 threads (16 warps, 32x64 each).
// O[i][c] = sum_j exp(S[i][j]-m) * Vt[c][j] / l; epilogue transposes to
// out[b][c][i] directly. grid (32, 1, 4).
// ---------------------------------------------------------------------------
__global__ void __launch_bounds__(512, 1) pv_mma(float* __restrict__ out)
{
    extern __shared__ char sm[];
    __shared__ float m_s[128], li_s[128];
    uint32_t sb = smem_u32(sm);
    int tid = threadIdx.x, wid = tid >> 5, lane = tid & 31;
    int b = blockIdx.z, i0 = blockIdx.x * 128;
    int wm = wid & 3, wn = wid >> 2;     // wn 0..3 (64 cols each of 256)

    const float* S = g_s + (size_t)b * NN * NN;
    const __nv_bfloat16* Vh = g_vth + (size_t)b * CC * NN;
    const __nv_bfloat16* Vl = g_vtl + (size_t)b * CC * NN;

    if (tid < 128) {
        m_s[tid]  = g_m[b * NN + i0 + tid];
        li_s[tid] = g_li[b * NN + i0 + tid];
    }

    // A producer: thread -> (row 0..127, 16B quad 0..3) of the 128x32 P tile
    int arow = tid >> 2, aq = tid & 3;
    const float* gS = S + (size_t)(i0 + arow) * NN + aq * 8;
    uint32_t s_aw = sb + arow * 80 + aq * 16;

    // B loader: thread -> (row 0..255, 32B half) of the 256x32 Vt tile
    int brow = tid >> 1, bhalf = (tid & 1) * 32;
    const char* gv_h = (const char*)(Vh + (size_t)brow * NN) + bhalf;
    const char* gv_l = (const char*)(Vl + (size_t)brow * NN) + bhalf;
    uint32_t s_b = sb + PV_BH + brow * 80 + bhalf;

    uint32_t a_off = (wm * 32 + (lane & 15)) * 80 + ((lane >> 4) << 4);
    uint32_t b_off = (wn * 64 + (lane & 7) + ((lane >> 4) << 3)) * 80
                   + (((lane >> 3) & 1) << 4) + PV_BH;

    float acc[2][8][4];
#pragma unroll
    for (int i = 0; i < 2; i++)
#pragma unroll
        for (int j = 0; j < 8; j++)
#pragma unroll
            for (int r = 0; r < 4; r++) acc[i][j][r] = 0.0f;

#define ISSUE_B(ch, stg) do {                                    \
        uint32_t d = s_b + (stg) * PV_STG;                       \
        size_t go = (size_t)(ch) * 64;                           \
        CP16(d,                        gv_h + go);               \
        CP16(d + 16,                   gv_h + go + 16);          \
        CP16(d + (PV_BL - PV_BH),      gv_l + go);               \
        CP16(d + (PV_BL - PV_BH) + 16, gv_l + go + 16);          \
        CP_COMMIT();                                             \
    } while (0)

    float4 sv[2];
    {
        const float4* p = (const float4*)gS;
        sv[0] = p[0]; sv[1] = p[1];
    }
    ISSUE_B(0, 0);
    __syncthreads();   // m_s ready

    float mrow = m_s[arow];

    for (int ch = 0; ch < 128; ch++) {
        int s = ch & 1;
        // write A tile (P hi/lo) for chunk ch from prefetched sv
        {
            union { __nv_bfloat16 e[8]; uint4 v; } uh, ul;
#pragma unroll
            for (int u = 0; u < 2; u++) {
                float e0 = fast_exp(sv[u].x - mrow);
                float e1 = fast_exp(sv[u].y - mrow);
                float e2 = fast_exp(sv[u].z - mrow);
                float e3 = fast_exp(sv[u].w - mrow);
                bf16_split(e0, uh.e[u * 4 + 0], ul.e[u * 4 + 0]);
                bf16_split(e1, uh.e[u * 4 + 1], ul.e[u * 4 + 1]);
                bf16_split(e2, uh.e[u * 4 + 2], ul.e[u * 4 + 2]);
                bf16_split(e3, uh.e[u * 4 + 3], ul.e[u * 4 + 3]);
            }
            uint32_t doff = (s_aw - sb) + s * PV_STG;
            *(uint4*)(sm + doff)         = uh.v;
            *(uint4*)(sm + doff + PV_AL) = ul.v;
        }
        if (ch < 127) {
            ISSUE_B(ch + 1, s ^ 1);
            const float4* p = (const float4*)(gS + (ch + 1) * 32);
            sv[0] = p[0]; sv[1] = p[1];
            CP_WAIT1();
        } else {
            CP_WAIT0();
        }
        __syncthreads();   // A(ch) visible + B(ch) landed
        mma_stage(sb + s * PV_STG, a_off, b_off, PV_AL, PV_BL - PV_BH, acc);
        __syncthreads();   // stage s consumed before A(ch+2)/B(ch+2) overwrite
    }
#undef ISSUE_B

    // Epilogue: scale by 1/l, transpose 128c x 128i halves via smem.
    float* smt = (float*)sm;   // 128 x 132 fp32 = 67584 B (reuses stages)
#pragma unroll
    for (int h = 0; h < 2; h++) {
        __syncthreads();
        if ((wn >> 1) == h) {
#pragma unroll
            for (int mi = 0; mi < 2; mi++) {
                int r0 = wm * 32 + mi * 16 + (lane >> 2);
                float l0 = li_s[r0], l1 = li_s[r0 + 8];
#pragma unroll
                for (int np = 0; np < 8; np++) {
                    int c = (wn & 1) * 64 + np * 8 + (lane & 3) * 2;
                    smt[(c + 0) * 132 + r0]     = acc[mi][np][0] * l0;
                    smt[(c + 1) * 132 + r0]     = acc[mi][np][1] * l0;
                    smt[(c + 0) * 132 + r0 + 8] = acc[mi][np][2] * l1;
                    smt[(c + 1) * 132 + r0 + 8] = acc[mi][np][3] * l1;
                }
            }
        }
        __syncthreads();
        {
            int cl = tid >> 2, part = tid & 3;
            float* op = out + ((size_t)b * CC + h * 128 + cl) * NN + i0 + part * 32;
            const float* sp = smt + cl * 132 + part * 32;
#pragma unroll
            for (int u = 0; u < 8; u++)
                ((float4*)op)[u] = ((const float4*)sp)[u];
        }
    }
}

extern "C" void kernel_launch(void* const* d_in, const int* in_sizes, int n_in,
                              void* d_out, int out_size)
{
    const float* x1 = (const float*)d_in[0];
    const float* x2 = (const float*)d_in[1];
    const float* Wq = (const float*)d_in[2];
    const float* bq = (const float*)d_in[3];
    const float* Wk = (const float*)d_in[4];
    const float* bk = (const float*)d_in[5];
    const float* Wv = (const float*)d_in[6];
    const float* bv = (const float*)d_in[7];
    float* out = (float*)d_out;

    cudaFuncSetAttribute(scores_mma, cudaFuncAttributeMaxDynamicSharedMemorySize, SC_SMEM);
    cudaFuncSetAttribute(pv_mma,     cudaFuncAttributeMaxDynamicSharedMemorySize, PV_SMEM);

    proj_kernel<<<dim3(NN / 128, CC / 128, BB * 3), 256>>>(x1, x2, Wq, bq, Wk, bk, Wv, bv);
    vprep_kernel<<<dim3(NN / 32, CC / 32, BB), dim3(32, 8)>>>();
    scores_mma<<<dim3(NN / 128, NN / 128, BB), 256, SC_SMEM>>>();
    merge_kernel<<<BB * NN / 8, 256>>>();
    pv_mma<<<dim3(NN / 128, 1, BB), 512, PV_SMEM>>>(out);
}

// round 5
// speedup vs baseline: 2.6213x; 1.1926x over previous
#include <cuda_runtime.h>
#include <cuda_bf16.h>
#include <cstdint>

#define BB 4
#define CC 256
#define NN 4096

__device__ __nv_bfloat16 g_x1h[(size_t)BB * NN * CC];
__device__ __nv_bfloat16 g_x1l[(size_t)BB * NN * CC];
__device__ __nv_bfloat16 g_x2h[(size_t)BB * NN * CC];
__device__ __nv_bfloat16 g_x2l[(size_t)BB * NN * CC];
__device__ __nv_bfloat16 g_wh[3 * CC * CC];
__device__ __nv_bfloat16 g_wl[3 * CC * CC];
__device__ float g_bias[3 * CC];
__device__ __nv_bfloat16 g_qh[(size_t)BB * NN * CC];
__device__ __nv_bfloat16 g_ql[(size_t)BB * NN * CC];
__device__ __nv_bfloat16 g_kh[(size_t)BB * NN * CC];
__device__ __nv_bfloat16 g_kl[(size_t)BB * NN * CC];
__device__ __nv_bfloat16 g_vth[(size_t)BB * CC * NN];
__device__ __nv_bfloat16 g_vtl[(size_t)BB * CC * NN];
__device__ float g_s[(size_t)BB * NN * NN];
__device__ float g_pm[(size_t)BB * NN * 16];
__device__ float g_pl[(size_t)BB * NN * 16];
__device__ float g_m [BB * NN];
__device__ float g_li[BB * NN];

__device__ __forceinline__ uint32_t smem_u32(const void* p) {
    uint32_t a;
    asm("{ .reg .u64 t; cvta.to.shared.u64 t, %1; cvt.u32.u64 %0, t; }"
        : "=r"(a) : "l"(p));
    return a;
}

#define CP16(smem, gptr) \
    asm volatile("cp.async.ca.shared.global [%0], [%1], 16;" \
                 :: "r"(smem), "l"(gptr) : "memory")
#define CP_COMMIT() asm volatile("cp.async.commit_group;" ::: "memory")
#define CP_WAIT1()  asm volatile("cp.async.wait_group 1;" ::: "memory")
#define CP_WAIT0()  asm volatile("cp.async.wait_group 0;" ::: "memory")

#define LDSM4(r0, r1, r2, r3, addr) \
    asm volatile("ldmatrix.sync.aligned.m8n8.x4.shared.b16 {%0,%1,%2,%3}, [%4];" \
                 : "=r"(r0), "=r"(r1), "=r"(r2), "=r"(r3) : "r"(addr))

__device__ __forceinline__ void mma_bf16(float* d, const uint32_t* a,
                                         uint32_t b0, uint32_t b1) {
    asm volatile(
        "mma.sync.aligned.m16n8k16.row.col.f32.bf16.bf16.f32 "
        "{%0,%1,%2,%3}, {%4,%5,%6,%7}, {%8,%9}, {%0,%1,%2,%3};"
        : "+f"(d[0]), "+f"(d[1]), "+f"(d[2]), "+f"(d[3])
        : "r"(a[0]), "r"(a[1]), "r"(a[2]), "r"(a[3]), "r"(b0), "r"(b1));
}

#define A_LO   10240
#define B_OFF  20480
#define B_LO   20480
#define STG    61440
#define SMEM_T (2 * STG)

__device__ __forceinline__ float fast_exp(float x) {
    float y = fmaxf(x, -87.0f) * 1.4426950408889634f;
    float z = __fadd_rn(y, 12582912.0f);
    int   k = __float_as_int(z) - 0x4B400000;
    float f = __fsub_rn(y, __fsub_rn(z, 12582912.0f));
    float p =             1.33335581e-3f;
    p = fmaf(p, f, 9.61812910e-3f);
    p = fmaf(p, f, 5.55041087e-2f);
    p = fmaf(p, f, 2.40226507e-1f);
    p = fmaf(p, f, 6.93147181e-1f);
    p = fmaf(p, f, 1.0f);
    return __int_as_float(__float_as_int(p) + (k << 23));
}

__device__ __forceinline__ void bf16_split(float v, __nv_bfloat16& h, __nv_bfloat16& l) {
    h = __float2bfloat16_rn(v);
    l = __float2bfloat16_rn(v - __bfloat162float(h));
}

__global__ void wsplit_kernel(const float* __restrict__ Wq,
                              const float* __restrict__ Wk,
                              const float* __restrict__ Wv)
{
    int t = blockIdx.y;
    const float* W = (t == 0) ? Wq : (t == 1) ? Wk : Wv;
    int idx = blockIdx.x * 256 + threadIdx.x;
    float v = W[idx];
    __nv_bfloat16 h, l;
    bf16_split(v, h, l);
    g_wh[t * CC * CC + idx] = h;
    g_wl[t * CC * CC + idx] = l;
}

__global__ void bias_copy_kernel(const float* __restrict__ bq,
                                 const float* __restrict__ bk,
                                 const float* __restrict__ bv)
{
    int i = threadIdx.x;
    g_bias[i]          = bq[i];
    g_bias[CC + i]     = bk[i];
    g_bias[2 * CC + i] = bv[i];
}

__global__ void xprep_kernel(const float* __restrict__ x1,
                             const float* __restrict__ x2)
{
    __shared__ float tile[32][33];
    int z = blockIdx.z;
    int b = z & 3;
    const float* src = ((z < 4) ? x1 : x2) + (size_t)b * CC * NN;
    __nv_bfloat16* dh = ((z < 4) ? g_x1h : g_x2h) + (size_t)b * NN * CC;
    __nv_bfloat16* dl = ((z < 4) ? g_x1l : g_x2l) + (size_t)b * NN * CC;
    int i0 = blockIdx.x * 32;
    int c0 = blockIdx.y * 32;
    int tx = threadIdx.x, ty = threadIdx.y;
#pragma unroll
    for (int u = 0; u < 32; u += 8)
        tile[ty + u][tx] = src[(size_t)(c0 + ty + u) * NN + i0 + tx];
    __syncthreads();
#pragma unroll
    for (int u = 0; u < 32; u += 8) {
        float v = tile[tx][ty + u];
        __nv_bfloat16 h, l;
        bf16_split(v, h, l);
        size_t idx = (size_t)(i0 + ty + u) * CC + c0 + tx;
        dh[idx] = h;
        dl[idx] = l;
    }
}

__device__ __forceinline__ void mma_stage(uint32_t st, uint32_t a_off, uint32_t b_off,
                                          float acc[2][8][4])
{
#pragma unroll
    for (int kk = 0; kk < 2; kk++) {
        uint32_t ah[2][4], al[2][4];
#pragma unroll
        for (int mi = 0; mi < 2; mi++) {
            uint32_t ad = st + a_off + mi * (16 * 80) + kk * 32;
            LDSM4(ah[mi][0], ah[mi][1], ah[mi][2], ah[mi][3], ad);
            LDSM4(al[mi][0], al[mi][1], al[mi][2], al[mi][3], ad + A_LO);
        }
#pragma unroll
        for (int ng = 0; ng < 4; ng++) {
            uint32_t bd = st + b_off + ng * (16 * 80) + kk * 32;
            uint32_t bh[4], bl[4];
            LDSM4(bh[0], bh[1], bh[2], bh[3], bd);
            LDSM4(bl[0], bl[1], bl[2], bl[3], bd + B_LO);
#pragma unroll
            for (int mi = 0; mi < 2; mi++) {
                mma_bf16(acc[mi][ng * 2],     ah[mi], bh[0], bh[1]);
                mma_bf16(acc[mi][ng * 2 + 1], ah[mi], bh[2], bh[3]);
                mma_bf16(acc[mi][ng * 2],     ah[mi], bl[0], bl[1]);
                mma_bf16(acc[mi][ng * 2 + 1], ah[mi], bl[2], bl[3]);
                mma_bf16(acc[mi][ng * 2],     al[mi], bh[0], bh[1]);
                mma_bf16(acc[mi][ng * 2 + 1], al[mi], bh[2], bh[3]);
            }
        }
    }
}

#define ISSUE_AB(stg, goff) do {                                  \
        uint32_t dA = s_a + (stg) * STG;                          \
        uint32_t dB = s_b + (stg) * STG;                          \
        CP16(dA,             gA_h + (goff));                      \
        CP16(dA + A_LO,      gA_l + (goff));                      \
        CP16(dB,             gB_h + (goff));                      \
        CP16(dB + 16,        gB_h + (goff) + 16);                 \
        CP16(dB + B_LO,      gB_l + (goff));                      \
        CP16(dB + B_LO + 16, gB_l + (goff) + 16);                 \
        CP_COMMIT();                                              \
    } while (0)

__global__ void __launch_bounds__(512, 1) proj_mma()
{
    extern __shared__ char sm[];
    __shared__ float bias_s[256];
    uint32_t sb = smem_u32(sm);
    int tid = threadIdx.x, wid = tid >> 5, lane = tid & 31;
    int z = blockIdx.z;
    int b = z / 3, t = z % 3;
    int i0 = blockIdx.x * 128;
    int wm = wid & 3, wn = wid >> 2;

    const __nv_bfloat16* Xh = ((t == 0) ? g_x1h : g_x2h) + (size_t)b * NN * CC;
    const __nv_bfloat16* Xl = ((t == 0) ? g_x1l : g_x2l) + (size_t)b * NN * CC;
    const __nv_bfloat16* Wh = g_wh + t * CC * CC;
    const __nv_bfloat16* Wl = g_wl + t * CC * CC;

    if (tid < 256) bias_s[tid] = g_bias[t * CC + tid];

    int arow = tid >> 2, aq = (tid & 3) * 16;
    const char* gA_h = (const char*)(Xh + (size_t)(i0 + arow) * CC) + aq;
    const char* gA_l = (const char*)(Xl + (size_t)(i0 + arow) * CC) + aq;
    uint32_t s_a = sb + arow * 80 + aq;
    int brow = tid >> 1, bhalf = (tid & 1) * 32;
    const char* gB_h = (const char*)(Wh + (size_t)brow * CC) + bhalf;
    const char* gB_l = (const char*)(Wl + (size_t)brow * CC) + bhalf;
    uint32_t s_b = sb + B_OFF + brow * 80 + bhalf;

    uint32_t a_off = (wm * 32 + (lane & 15)) * 80 + ((lane >> 4) << 4);
    uint32_t b_off = (wn * 64 + (lane & 7) + ((lane >> 4) << 3)) * 80
                   + (((lane >> 3) & 1) << 4) + B_OFF;

    float acc[2][8][4];
#pragma unroll
    for (int i = 0; i < 2; i++)
#pragma unroll
        for (int j = 0; j < 8; j++)
#pragma unroll
            for (int r = 0; r < 4; r++) acc[i][j][r] = 0.0f;

    ISSUE_AB(0, 0);
#pragma unroll 2
    for (int ch = 0; ch < 8; ch++) {
        int s = ch & 1;
        if (ch < 7) { ISSUE_AB(s ^ 1, (size_t)(ch + 1) * 64); CP_WAIT1(); }
        else        { CP_WAIT0(); }
        __syncthreads();
        mma_stage(sb + s * STG, a_off, b_off, acc);
        __syncthreads();
    }

    if (t < 2) {
        __nv_bfloat16* dh = ((t == 0) ? g_qh : g_kh) + (size_t)b * NN * CC;
        __nv_bfloat16* dl = ((t == 0) ? g_ql : g_kl) + (size_t)b * NN * CC;
#pragma unroll
        for (int mi = 0; mi < 2; mi++) {
#pragma unroll
            for (int np = 0; np < 8; np++) {
                int col = wn * 64 + np * 8 + (lane & 3) * 2;
                float bc0 = bias_s[col], bc1 = bias_s[col + 1];
#pragma unroll
                for (int rh = 0; rh < 2; rh++) {
                    int row = i0 + wm * 32 + mi * 16 + rh * 8 + (lane >> 2);
                    float v0 = acc[mi][np][rh * 2]     + bc0;
                    float v1 = acc[mi][np][rh * 2 + 1] + bc1;
                    __nv_bfloat16 h0, l0, h1, l1;
                    bf16_split(v0, h0, l0);
                    bf16_split(v1, h1, l1);
                    union { __nv_bfloat16 e[2]; uint32_t u; } ph, pl;
                    ph.e[0] = h0; ph.e[1] = h1;
                    pl.e[0] = l0; pl.e[1] = l1;
                    *(uint32_t*)(dh + (size_t)row * CC + col) = ph.u;
                    *(uint32_t*)(dl + (size_t)row * CC + col) = pl.u;
                }
            }
        }
    } else {
        __nv_bfloat16* dh = g_vth + (size_t)b * CC * NN;
        __nv_bfloat16* dl = g_vtl + (size_t)b * CC * NN;
        float* smt = (float*)sm;
#pragma unroll
        for (int h = 0; h < 2; h++) {
            __syncthreads();
            if ((wn >> 1) == h) {
#pragma unroll
                for (int mi = 0; mi < 2; mi++) {
                    int r0 = wm * 32 + mi * 16 + (lane >> 2);
#pragma unroll
                    for (int np = 0; np < 8; np++) {
                        int cl = (wn & 1) * 64 + np * 8 + (lane & 3) * 2;
                        float b0 = bias_s[h * 128 + cl], b1 = bias_s[h * 128 + cl + 1];
                        smt[(cl + 0) * 132 + r0]     = acc[mi][np][0] + b0;
                        smt[(cl + 1) * 132 + r0]     = acc[mi][np][1] + b1;
                        smt[(cl + 0) * 132 + r0 + 8] = acc[mi][np][2] + b0;
                        smt[(cl + 1) * 132 + r0 + 8] = acc[mi][np][3] + b1;
                    }
                }
            }
            __syncthreads();
            {
                int cl = tid >> 2, part = tid & 3;
                const float* sp = smt + cl * 132 + part * 32;
                size_t go = (size_t)(h * 128 + cl) * NN + i0 + part * 32;
                union { __nv_bfloat16 e[32]; uint4 v[4]; } uh, ul;
#pragma unroll
                for (int u = 0; u < 32; u++) {
                    __nv_bfloat16 hh, ll;
                    bf16_split(sp[u], hh, ll);
                    uh.e[u] = hh; ul.e[u] = ll;
                }
#pragma unroll
                for (int u = 0; u < 4; u++) {
                    *(uint4*)(dh + go + u * 8) = uh.v[u];
                    *(uint4*)(dl + go + u * 8) = ul.v[u];
                }
            }
        }
    }
}

__global__ void __launch_bounds__(512, 1) scores_mma()
{
    extern __shared__ char sm[];
    __shared__ float pm[128][4], pl[128][4];
    uint32_t sb = smem_u32(sm);
    int tid = threadIdx.x, wid = tid >> 5, lane = tid & 31;
    int b = blockIdx.z, i0 = blockIdx.x * 128, j0 = blockIdx.y * 256;
    int wm = wid & 3, wn = wid >> 2;

    const __nv_bfloat16* Qh = g_qh + (size_t)b * NN * CC;
    const __nv_bfloat16* Ql = g_ql + (size_t)b * NN * CC;
    const __nv_bfloat16* Kh = g_kh + (size_t)b * NN * CC;
    const __nv_bfloat16* Kl = g_kl + (size_t)b * NN * CC;
    float* S = g_s + (size_t)b * NN * NN;

    int arow = tid >> 2, aq = (tid & 3) * 16;
    const char* gA_h = (const char*)(Qh + (size_t)(i0 + arow) * CC) + aq;
    const char* gA_l = (const char*)(Ql + (size_t)(i0 + arow) * CC) + aq;
    uint32_t s_a = sb + arow * 80 + aq;
    int brow = tid >> 1, bhalf = (tid & 1) * 32;
    const char* gB_h = (const char*)(Kh + (size_t)(j0 + brow) * CC) + bhalf;
    const char* gB_l = (const char*)(Kl + (size_t)(j0 + brow) * CC) + bhalf;
    uint32_t s_b = sb + B_OFF + brow * 80 + bhalf;

    uint32_t a_off = (wm * 32 + (lane & 15)) * 80 + ((lane >> 4) << 4);
    uint32_t b_off = (wn * 64 + (lane & 7) + ((lane >> 4) << 3)) * 80
                   + (((lane >> 3) & 1) << 4) + B_OFF;

    float acc[2][8][4];
#pragma unroll
    for (int i = 0; i < 2; i++)
#pragma unroll
        for (int j = 0; j < 8; j++)
#pragma unroll
            for (int r = 0; r < 4; r++) acc[i][j][r] = 0.0f;

    ISSUE_AB(0, 0);
#pragma unroll 2
    for (int ch = 0; ch < 8; ch++) {
        int s = ch & 1;
        if (ch < 7) { ISSUE_AB(s ^ 1, (size_t)(ch + 1) * 64); CP_WAIT1(); }
        else        { CP_WAIT0(); }
        __syncthreads();
        mma_stage(sb + s * STG, a_off, b_off, acc);
        __syncthreads();
    }

#pragma unroll
    for (int mi = 0; mi < 2; mi++) {
        int row = i0 + wm * 32 + mi * 16 + (lane >> 2);
#pragma unroll
        for (int np = 0; np < 8; np++) {
            int col = j0 + wn * 64 + np * 8 + (lane & 3) * 2;
            *(float2*)(S + (size_t)row * NN + col) =
                make_float2(acc[mi][np][0], acc[mi][np][1]);
            *(float2*)(S + (size_t)(row + 8) * NN + col) =
                make_float2(acc[mi][np][2], acc[mi][np][3]);
        }
    }

    int q = lane >> 2, qt = lane & 3;
    float mloc[2][2];
#pragma unroll
    for (int mi = 0; mi < 2; mi++)
#pragma unroll
        for (int rh = 0; rh < 2; rh++) {
            float m = -1e30f;
#pragma unroll
            for (int np = 0; np < 8; np++)
                m = fmaxf(m, fmaxf(acc[mi][np][rh * 2], acc[mi][np][rh * 2 + 1]));
            mloc[mi][rh] = m;
        }
#pragma unroll
    for (int d = 1; d <= 2; d <<= 1)
#pragma unroll
        for (int mi = 0; mi < 2; mi++)
#pragma unroll
            for (int rh = 0; rh < 2; rh++)
                mloc[mi][rh] = fmaxf(mloc[mi][rh],
                                     __shfl_xor_sync(0xffffffffu, mloc[mi][rh], d));
    if (qt == 0)
#pragma unroll
        for (int mi = 0; mi < 2; mi++)
#pragma unroll
            for (int rh = 0; rh < 2; rh++)
                pm[wm * 32 + mi * 16 + rh * 8 + q][wn] = mloc[mi][rh];
    __syncthreads();
    float mrow[2][2], srow[2][2];
#pragma unroll
    for (int mi = 0; mi < 2; mi++)
#pragma unroll
        for (int rh = 0; rh < 2; rh++) {
            int row = wm * 32 + mi * 16 + rh * 8 + q;
            float m = fmaxf(fmaxf(pm[row][0], pm[row][1]),
                            fmaxf(pm[row][2], pm[row][3]));
            mrow[mi][rh] = m;
            float s = 0.0f;
#pragma unroll
            for (int np = 0; np < 8; np++)
                s += fast_exp(acc[mi][np][rh * 2] - m)
                   + fast_exp(acc[mi][np][rh * 2 + 1] - m);
            srow[mi][rh] = s;
        }
#pragma unroll
    for (int d = 1; d <= 2; d <<= 1)
#pragma unroll
        for (int mi = 0; mi < 2; mi++)
#pragma unroll
            for (int rh = 0; rh < 2; rh++)
                srow[mi][rh] += __shfl_xor_sync(0xffffffffu, srow[mi][rh], d);
    if (qt == 0)
#pragma unroll
        for (int mi = 0; mi < 2; mi++)
#pragma unroll
            for (int rh = 0; rh < 2; rh++)
                pl[wm * 32 + mi * 16 + rh * 8 + q][wn] = srow[mi][rh];
    __syncthreads();
    if (qt == 0 && wn == 0)
#pragma unroll
        for (int mi = 0; mi < 2; mi++)
#pragma unroll
            for (int rh = 0; rh < 2; rh++) {
                int row = wm * 32 + mi * 16 + rh * 8 + q;
                size_t idx = ((size_t)b * NN + i0 + row) * 16 + blockIdx.y;
                g_pm[idx] = mrow[mi][rh];
                g_pl[idx] = pl[row][0] + pl[row][1] + pl[row][2] + pl[row][3];
            }
}

__global__ __launch_bounds__(256) void merge_kernel()
{
    int row = blockIdx.x * 16 + (threadIdx.x >> 4);
    int sub = threadIdx.x & 15;
    float m_t = g_pm[(size_t)row * 16 + sub];
    float l_t = g_pl[(size_t)row * 16 + sub];
    float m = m_t;
#pragma unroll
    for (int d = 8; d > 0; d >>= 1) m = fmaxf(m, __shfl_xor_sync(0xffffffffu, m, d));
    float l = l_t * fast_exp(m_t - m);
#pragma unroll
    for (int d = 8; d > 0; d >>= 1) l += __shfl_xor_sync(0xffffffffu, l, d);
    if (sub == 0) { g_m[row] = m; g_li[row] = 1.0f / l; }
}

__global__ void __launch_bounds__(512, 1) pv_mma(float* __restrict__ out)
{
    extern __shared__ char sm[];
    __shared__ float m_s[128], li_s[128];
    uint32_t sb = smem_u32(sm);
    int tid = threadIdx.x, wid = tid >> 5, lane = tid & 31;
    int b = blockIdx.z, i0 = blockIdx.x * 128;
    int wm = wid & 3, wn = wid >> 2;

    const float* S = g_s + (size_t)b * NN * NN;
    const __nv_bfloat16* Vh = g_vth + (size_t)b * CC * NN;
    const __nv_bfloat16* Vl = g_vtl + (size_t)b * CC * NN;

    if (tid < 128) {
        m_s[tid]  = g_m[b * NN + i0 + tid];
        li_s[tid] = g_li[b * NN + i0 + tid];
    }

    int arow = tid >> 2, aq = tid & 3;
    const float* gS = S + (size_t)(i0 + arow) * NN + aq * 8;
    uint32_t s_aw = sb + arow * 80 + aq * 16;

    int brow = tid >> 1, bhalf = (tid & 1) * 32;
    const char* gv_h = (const char*)(Vh + (size_t)brow * NN) + bhalf;
    const char* gv_l = (const char*)(Vl + (size_t)brow * NN) + bhalf;
    uint32_t s_b = sb + B_OFF + brow * 80 + bhalf;

    uint32_t a_off = (wm * 32 + (lane & 15)) * 80 + ((lane >> 4) << 4);
    uint32_t b_off = (wn * 64 + (lane & 7) + ((lane >> 4) << 3)) * 80
                   + (((lane >> 3) & 1) << 4) + B_OFF;

    float acc[2][8][4];
#pragma unroll
    for (int i = 0; i < 2; i++)
#pragma unroll
        for (int j = 0; j < 8; j++)
#pragma unroll
            for (int r = 0; r < 4; r++) acc[i][j][r] = 0.0f;

#define ISSUE_B(ch, stg) do {                                    \
        uint32_t d = s_b + (stg) * STG;                          \
        size_t go = (size_t)(ch) * 64;                           \
        CP16(d,             gv_h + go);                          \
        CP16(d + 16,        gv_h + go + 16);                     \
        CP16(d + B_LO,      gv_l + go);                          \
        CP16(d + B_LO + 16, gv_l + go + 16);                     \
        CP_COMMIT();                                             \
    } while (0)

    float4 sv[2];
    {
        const float4* p = (const float4*)gS;
        sv[0] = p[0]; sv[1] = p[1];
    }
    ISSUE_B(0, 0);
    __syncthreads();

    float mrow = m_s[arow];

    for (int ch = 0; ch < 128; ch++) {
        int s = ch & 1;
        {
            union { __nv_bfloat16 e[8]; uint4 v; } uh, ul;
#pragma unroll
            for (int u = 0; u < 2; u++) {
                float e0 = fast_exp(sv[u].x - mrow);
                float e1 = fast_exp(sv[u].y - mrow);
                float e2 = fast_exp(sv[u].z - mrow);
                float e3 = fast_exp(sv[u].w - mrow);
                bf16_split(e0, uh.e[u * 4 + 0], ul.e[u * 4 + 0]);
                bf16_split(e1, uh.e[u * 4 + 1], ul.e[u * 4 + 1]);
                bf16_split(e2, uh.e[u * 4 + 2], ul.e[u * 4 + 2]);
                bf16_split(e3, uh.e[u * 4 + 3], ul.e[u * 4 + 3]);
            }
            uint32_t doff = (s_aw - sb) + s * STG;
            *(uint4*)(sm + doff)        = uh.v;
            *(uint4*)(sm + doff + A_LO) = ul.v;
        }
        if (ch < 127) {
            ISSUE_B(ch + 1, s ^ 1);
            const float4* p = (const float4*)(gS + (ch + 1) * 32);
            sv[0] = p[0]; sv[1] = p[1];
            CP_WAIT1();
        } else {
            CP_WAIT0();
        }
        __syncthreads();
        mma_stage(sb + s * STG, a_off, b_off, acc);
        __syncthreads();
    }
#undef ISSUE_B

    float* smt = (float*)sm;
#pragma unroll
    for (int h = 0; h < 2; h++) {
        __syncthreads();
        if ((wn >> 1) == h) {
#pragma unroll
            for (int mi = 0; mi < 2; mi++) {
                int r0 = wm * 32 + mi * 16 + (lane >> 2);
                float l0 = li_s[r0], l1 = li_s[r0 + 8];
#pragma unroll
                for (int np = 0; np < 8; np++) {
                    int c = (wn & 1) * 64 + np * 8 + (lane & 3) * 2;
                    smt[(c + 0) * 132 + r0]     = acc[mi][np][0] * l0;
                    smt[(c + 1) * 132 + r0]     = acc[mi][np][1] * l0;
                    smt[(c + 0) * 132 + r0 + 8] = acc[mi][np][2] * l1;
                    smt[(c + 1) * 132 + r0 + 8] = acc[mi][np][3] * l1;
                }
            }
        }
        __syncthreads();
        {
            int cl = tid >> 2, part = tid & 3;
            float* op = out + ((size_t)b * CC + h * 128 + cl) * NN + i0 + part * 32;
            const float* sp = smt + cl * 132 + part * 32;
#pragma unroll
            for (int u = 0; u < 8; u++)
                ((float4*)op)[u] = ((const float4*)sp)[u];
        }
    }
}

extern "C" void kernel_launch(void* const* d_in, const int* in_sizes, int n_in,
                              void* d_out, int out_size)
{
    const float* x1 = (const float*)d_in[0];
    const float* x2 = (const float*)d_in[1];
    const float* Wq = (const float*)d_in[2];
    const float* bq = (const float*)d_in[3];
    const float* Wk = (const float*)d_in[4];
    const float* bk = (const float*)d_in[5];
    const float* Wv = (const float*)d_in[6];
    const float* bv = (const float*)d_in[7];
    float* out = (float*)d_out;

    cudaFuncSetAttribute(proj_mma,   cudaFuncAttributeMaxDynamicSharedMemorySize, SMEM_T);
    cudaFuncSetAttribute(scores_mma, cudaFuncAttributeMaxDynamicSharedMemorySize, SMEM_T);
    cudaFuncSetAttribute(pv_mma,     cudaFuncAttributeMaxDynamicSharedMemorySize, SMEM_T);

    wsplit_kernel<<<dim3(256, 3), 256>>>(Wq, Wk, Wv);
    bias_copy_kernel<<<1, 256>>>(bq, bk, bv);
    xprep_kernel<<<dim3(NN / 32, CC / 32, 2 * BB), dim3(32, 8)>>>(x1, x2);
    proj_mma<<<dim3(NN / 128, 1, BB * 3), 512, SMEM_T>>>();
    scores_mma<<<dim3(NN / 128, NN / 256, BB), 512, SMEM_T>>>();
    merge_kernel<<<BB * NN / 16, 256>>>();
    pv_mma<<<dim3(NN / 128, 1, BB), 512, SMEM_T>>>(out);
}

// round 6
// speedup vs baseline: 3.0043x; 1.1461x over previous
#include <cuda_runtime.h>
#include <cuda_fp16.h>
#include <cstdint>

#define BB 4
#define CC 256
#define NN 4096

// ---------------------------------------------------------------------------
// Scratch (allocation-free: __device__ bss). All operands fp16.
// ---------------------------------------------------------------------------
__device__ __half g_x1h[(size_t)BB * NN * CC];
__device__ __half g_x1l[(size_t)BB * NN * CC];
__device__ __half g_x2h[(size_t)BB * NN * CC];
__device__ __half g_x2l[(size_t)BB * NN * CC];
__device__ __half g_wh[3 * CC * CC];
__device__ __half g_wl[3 * CC * CC];
__device__ float  g_bias[3 * CC];
__device__ __half g_qh[(size_t)BB * NN * CC];
__device__ __half g_ql[(size_t)BB * NN * CC];
__device__ __half g_kh[(size_t)BB * NN * CC];
__device__ __half g_kl[(size_t)BB * NN * CC];
__device__ __half g_vt[(size_t)BB * CC * NN];     // V^T single fp16 [b][c][j]
__device__ float g_s[(size_t)BB * NN * NN];       // scores fp32 (256 MB)
__device__ float g_pm[(size_t)BB * NN * 16];
__device__ float g_pl[(size_t)BB * NN * 16];
__device__ float g_m [BB * NN];
__device__ float g_li[BB * NN];

// ---------------------------------------------------------------------------
// PTX helpers
// ---------------------------------------------------------------------------
__device__ __forceinline__ uint32_t smem_u32(const void* p) {
    uint32_t a;
    asm("{ .reg .u64 t; cvta.to.shared.u64 t, %1; cvt.u32.u64 %0, t; }"
        : "=r"(a) : "l"(p));
    return a;
}

#define CP16(smem, gptr) \
    asm volatile("cp.async.ca.shared.global [%0], [%1], 16;" \
                 :: "r"(smem), "l"(gptr) : "memory")
#define CP_COMMIT() asm volatile("cp.async.commit_group;" ::: "memory")
#define CP_WAIT1()  asm volatile("cp.async.wait_group 1;" ::: "memory")
#define CP_WAIT0()  asm volatile("cp.async.wait_group 0;" ::: "memory")

#define LDSM4(r0, r1, r2, r3, addr) \
    asm volatile("ldmatrix.sync.aligned.m8n8.x4.shared.b16 {%0,%1,%2,%3}, [%4];" \
                 : "=r"(r0), "=r"(r1), "=r"(r2), "=r"(r3) : "r"(addr))

__device__ __forceinline__ void mma_f16(float* d, const uint32_t* a,
                                        uint32_t b0, uint32_t b1) {
    asm volatile(
        "mma.sync.aligned.m16n8k16.row.col.f32.f16.f16.f32 "
        "{%0,%1,%2,%3}, {%4,%5,%6,%7}, {%8,%9}, {%0,%1,%2,%3};"
        : "+f"(d[0]), "+f"(d[1]), "+f"(d[2]), "+f"(d[3])
        : "r"(a[0]), "r"(a[1]), "r"(a[2]), "r"(a[3]), "r"(b0), "r"(b1));
}

// k-chunk 32 fp16, 80B-padded rows (conflict-free ldmatrix).
// scores/proj stage: Ah(10240) Al(10240) Bh(20480) Bl(20480) = 61440, x3
#define A_LO    10240
#define B_OFF   20480
#define B_LO    20480
#define STG     61440
#define SMEM_S  (3 * STG)      // 184320
// pv stage: Ph(10240) Pl(10240) V(20480) = 40960, x3
#define PA_LO   10240
#define PB_OFF  20480
#define PSTG    40960
#define SMEM_P  (3 * PSTG)     // 122880

__device__ __forceinline__ float fast_exp(float x) {
    float y = fmaxf(x, -87.0f) * 1.4426950408889634f;
    float z = __fadd_rn(y, 12582912.0f);
    int   k = __float_as_int(z) - 0x4B400000;
    float f = __fsub_rn(y, __fsub_rn(z, 12582912.0f));
    float p =             1.33335581e-3f;
    p = fmaf(p, f, 9.61812910e-3f);
    p = fmaf(p, f, 5.55041087e-2f);
    p = fmaf(p, f, 2.40226507e-1f);
    p = fmaf(p, f, 6.93147181e-1f);
    p = fmaf(p, f, 1.0f);
    return __int_as_float(__float_as_int(p) + (k << 23));
}

__device__ __forceinline__ void f16_split(float v, __half& h, __half& l) {
    h = __float2half_rn(v);
    l = __float2half_rn(v - __half2float(h));
}

// ---------------------------------------------------------------------------
// Prep kernels
// ---------------------------------------------------------------------------
__global__ void wsplit_kernel(const float* __restrict__ Wq,
                              const float* __restrict__ Wk,
                              const float* __restrict__ Wv)
{
    int t = blockIdx.y;
    const float* W = (t == 0) ? Wq : (t == 1) ? Wk : Wv;
    int idx = blockIdx.x * 256 + threadIdx.x;
    float v = W[idx];
    __half h, l;
    f16_split(v, h, l);
    g_wh[t * CC * CC + idx] = h;
    g_wl[t * CC * CC + idx] = l;
}

__global__ void bias_copy_kernel(const float* __restrict__ bq,
                                 const float* __restrict__ bk,
                                 const float* __restrict__ bv)
{
    int i = threadIdx.x;
    g_bias[i]          = bq[i];
    g_bias[CC + i]     = bk[i];
    g_bias[2 * CC + i] = bv[i];
}

__global__ void xprep_kernel(const float* __restrict__ x1,
                             const float* __restrict__ x2)
{
    __shared__ float tile[32][33];
    int z = blockIdx.z;
    int b = z & 3;
    const float* src = ((z < 4) ? x1 : x2) + (size_t)b * CC * NN;
    __half* dh = ((z < 4) ? g_x1h : g_x2h) + (size_t)b * NN * CC;
    __half* dl = ((z < 4) ? g_x1l : g_x2l) + (size_t)b * NN * CC;
    int i0 = blockIdx.x * 32;
    int c0 = blockIdx.y * 32;
    int tx = threadIdx.x, ty = threadIdx.y;
#pragma unroll
    for (int u = 0; u < 32; u += 8)
        tile[ty + u][tx] = src[(size_t)(c0 + ty + u) * NN + i0 + tx];
    __syncthreads();
#pragma unroll
    for (int u = 0; u < 32; u += 8) {
        float v = tile[tx][ty + u];
        __half h, l;
        f16_split(v, h, l);
        size_t idx = (size_t)(i0 + ty + u) * CC + c0 + tx;
        dh[idx] = h;
        dl[idx] = l;
    }
}

// ---------------------------------------------------------------------------
// Warp MMA: 3-term (A hi/lo x B hi/lo, drop lo*lo), warp tile 32x64.
// ---------------------------------------------------------------------------
__device__ __forceinline__ void mma_stage3(uint32_t st, uint32_t a_off, uint32_t b_off,
                                           float acc[2][8][4])
{
#pragma unroll
    for (int kk = 0; kk < 2; kk++) {
        uint32_t ah[2][4], al[2][4];
#pragma unroll
        for (int mi = 0; mi < 2; mi++) {
            uint32_t ad = st + a_off + mi * (16 * 80) + kk * 32;
            LDSM4(ah[mi][0], ah[mi][1], ah[mi][2], ah[mi][3], ad);
            LDSM4(al[mi][0], al[mi][1], al[mi][2], al[mi][3], ad + A_LO);
        }
#pragma unroll
        for (int ng = 0; ng < 4; ng++) {
            uint32_t bd = st + b_off + ng * (16 * 80) + kk * 32;
            uint32_t bh[4], bl[4];
            LDSM4(bh[0], bh[1], bh[2], bh[3], bd);
            LDSM4(bl[0], bl[1], bl[2], bl[3], bd + B_LO);
#pragma unroll
            for (int mi = 0; mi < 2; mi++) {
                mma_f16(acc[mi][ng * 2],     ah[mi], bh[0], bh[1]);
                mma_f16(acc[mi][ng * 2 + 1], ah[mi], bh[2], bh[3]);
                mma_f16(acc[mi][ng * 2],     ah[mi], bl[0], bl[1]);
                mma_f16(acc[mi][ng * 2 + 1], ah[mi], bl[2], bl[3]);
                mma_f16(acc[mi][ng * 2],     al[mi], bh[0], bh[1]);
                mma_f16(acc[mi][ng * 2 + 1], al[mi], bh[2], bh[3]);
            }
        }
    }
}

// 2-term PV: (Ph + Pl) x V(single fp16).
__device__ __forceinline__ void mma_stage2(uint32_t st, uint32_t a_off, uint32_t b_off,
                                           float acc[2][8][4])
{
#pragma unroll
    for (int kk = 0; kk < 2; kk++) {
        uint32_t ah[2][4], al[2][4];
#pragma unroll
        for (int mi = 0; mi < 2; mi++) {
            uint32_t ad = st + a_off + mi * (16 * 80) + kk * 32;
            LDSM4(ah[mi][0], ah[mi][1], ah[mi][2], ah[mi][3], ad);
            LDSM4(al[mi][0], al[mi][1], al[mi][2], al[mi][3], ad + PA_LO);
        }
#pragma unroll
        for (int ng = 0; ng < 4; ng++) {
            uint32_t bd = st + b_off + ng * (16 * 80) + kk * 32;
            uint32_t bh[4];
            LDSM4(bh[0], bh[1], bh[2], bh[3], bd);
#pragma unroll
            for (int mi = 0; mi < 2; mi++) {
                mma_f16(acc[mi][ng * 2],     ah[mi], bh[0], bh[1]);
                mma_f16(acc[mi][ng * 2 + 1], ah[mi], bh[2], bh[3]);
                mma_f16(acc[mi][ng * 2],     al[mi], bh[0], bh[1]);
                mma_f16(acc[mi][ng * 2 + 1], al[mi], bh[2], bh[3]);
            }
        }
    }
}

// Loader: A (128 rows x 64B hi+lo), B (256 rows x 64B hi+lo). 512 threads.
#define ISSUE_AB(stg_base, goff) do {                             \
        uint32_t dA = s_a + (stg_base);                           \
        uint32_t dB = s_b + (stg_base);                           \
        CP16(dA,             gA_h + (goff));                      \
        CP16(dA + A_LO,      gA_l + (goff));                      \
        CP16(dB,             gB_h + (goff));                      \
        CP16(dB + 16,        gB_h + (goff) + 16);                 \
        CP16(dB + B_LO,      gB_l + (goff));                      \
        CP16(dB + B_LO + 16, gB_l + (goff) + 16);                 \
        CP_COMMIT();                                              \
    } while (0)

// ---------------------------------------------------------------------------
// Kernel: QKV projection via mma (fp16 3-term). grid (32,1,12), 512 thr.
// ---------------------------------------------------------------------------
__global__ void __launch_bounds__(512, 1) proj_mma()
{
    extern __shared__ char sm[];
    __shared__ float bias_s[256];
    uint32_t sb = smem_u32(sm);
    int tid = threadIdx.x, wid = tid >> 5, lane = tid & 31;
    int z = blockIdx.z;
    int b = z / 3, t = z % 3;
    int i0 = blockIdx.x * 128;
    int wm = wid & 3, wn = wid >> 2;

    const __half* Xh = ((t == 0) ? g_x1h : g_x2h) + (size_t)b * NN * CC;
    const __half* Xl = ((t == 0) ? g_x1l : g_x2l) + (size_t)b * NN * CC;
    const __half* Wh = g_wh + t * CC * CC;
    const __half* Wl = g_wl + t * CC * CC;

    if (tid < 256) bias_s[tid] = g_bias[t * CC + tid];

    int arow = tid >> 2, aq = (tid & 3) * 16;
    const char* gA_h = (const char*)(Xh + (size_t)(i0 + arow) * CC) + aq;
    const char* gA_l = (const char*)(Xl + (size_t)(i0 + arow) * CC) + aq;
    uint32_t s_a = sb + arow * 80 + aq;
    int brow = tid >> 1, bhalf = (tid & 1) * 32;
    const char* gB_h = (const char*)(Wh + (size_t)brow * CC) + bhalf;
    const char* gB_l = (const char*)(Wl + (size_t)brow * CC) + bhalf;
    uint32_t s_b = sb + B_OFF + brow * 80 + bhalf;

    uint32_t a_off = (wm * 32 + (lane & 15)) * 80 + ((lane >> 4) << 4);
    uint32_t b_off = (wn * 64 + (lane & 7) + ((lane >> 4) << 3)) * 80
                   + (((lane >> 3) & 1) << 4) + B_OFF;

    float acc[2][8][4];
#pragma unroll
    for (int i = 0; i < 2; i++)
#pragma unroll
        for (int j = 0; j < 8; j++)
#pragma unroll
            for (int r = 0; r < 4; r++) acc[i][j][r] = 0.0f;

    ISSUE_AB(0, 0);
    ISSUE_AB(STG, 64);
    uint32_t bA = 0, bB = STG, bC = 2 * STG;
    for (int ch = 0; ch < 8; ch++) {
        if (ch < 7) CP_WAIT1(); else CP_WAIT0();
        __syncthreads();
        if (ch < 6) ISSUE_AB(bC, (size_t)(ch + 2) * 64);
        mma_stage3(sb + bA, a_off, b_off, acc);
        uint32_t tmp = bA; bA = bB; bB = bC; bC = tmp;
    }

    if (t < 2) {
        __half* dh = ((t == 0) ? g_qh : g_kh) + (size_t)b * NN * CC;
        __half* dl = ((t == 0) ? g_ql : g_kl) + (size_t)b * NN * CC;
#pragma unroll
        for (int mi = 0; mi < 2; mi++) {
#pragma unroll
            for (int np = 0; np < 8; np++) {
                int col = wn * 64 + np * 8 + (lane & 3) * 2;
                float bc0 = bias_s[col], bc1 = bias_s[col + 1];
#pragma unroll
                for (int rh = 0; rh < 2; rh++) {
                    int row = i0 + wm * 32 + mi * 16 + rh * 8 + (lane >> 2);
                    float v0 = acc[mi][np][rh * 2]     + bc0;
                    float v1 = acc[mi][np][rh * 2 + 1] + bc1;
                    __half h0, l0, h1, l1;
                    f16_split(v0, h0, l0);
                    f16_split(v1, h1, l1);
                    union { __half e[2]; uint32_t u; } ph, pl;
                    ph.e[0] = h0; ph.e[1] = h1;
                    pl.e[0] = l0; pl.e[1] = l1;
                    *(uint32_t*)(dh + (size_t)row * CC + col) = ph.u;
                    *(uint32_t*)(dl + (size_t)row * CC + col) = pl.u;
                }
            }
        }
    } else {
        __half* dv = g_vt + (size_t)b * CC * NN;
        float* smt = (float*)sm;
#pragma unroll
        for (int h = 0; h < 2; h++) {
            __syncthreads();
            if ((wn >> 1) == h) {
#pragma unroll
                for (int mi = 0; mi < 2; mi++) {
                    int r0 = wm * 32 + mi * 16 + (lane >> 2);
#pragma unroll
                    for (int np = 0; np < 8; np++) {
                        int cl = (wn & 1) * 64 + np * 8 + (lane & 3) * 2;
                        float b0 = bias_s[h * 128 + cl], b1 = bias_s[h * 128 + cl + 1];
                        smt[(cl + 0) * 132 + r0]     = acc[mi][np][0] + b0;
                        smt[(cl + 1) * 132 + r0]     = acc[mi][np][1] + b1;
                        smt[(cl + 0) * 132 + r0 + 8] = acc[mi][np][2] + b0;
                        smt[(cl + 1) * 132 + r0 + 8] = acc[mi][np][3] + b1;
                    }
                }
            }
            __syncthreads();
            {
                int cl = tid >> 2, part = tid & 3;
                const float* sp = smt + cl * 132 + part * 32;
                size_t go = (size_t)(h * 128 + cl) * NN + i0 + part * 32;
                union { __half e[32]; uint4 v[4]; } uh;
#pragma unroll
                for (int u = 0; u < 32; u++) uh.e[u] = __float2half_rn(sp[u]);
#pragma unroll
                for (int u = 0; u < 4; u++)
                    *(uint4*)(dv + go + u * 8) = uh.v[u];
            }
        }
    }
}

// ---------------------------------------------------------------------------
// Kernel: scores S = Q.K^T (fp16 3-term) + fused partial softmax stats.
// grid (32, 16, 4), 512 threads.
// ---------------------------------------------------------------------------
__global__ void __launch_bounds__(512, 1) scores_mma()
{
    extern __shared__ char sm[];
    __shared__ float pm[128][4], pl[128][4];
    uint32_t sb = smem_u32(sm);
    int tid = threadIdx.x, wid = tid >> 5, lane = tid & 31;
    int b = blockIdx.z, i0 = blockIdx.x * 128, j0 = blockIdx.y * 256;
    int wm = wid & 3, wn = wid >> 2;

    const __half* Qh = g_qh + (size_t)b * NN * CC;
    const __half* Ql = g_ql + (size_t)b * NN * CC;
    const __half* Kh = g_kh + (size_t)b * NN * CC;
    const __half* Kl = g_kl + (size_t)b * NN * CC;
    float* S = g_s + (size_t)b * NN * NN;

    int arow = tid >> 2, aq = (tid & 3) * 16;
    const char* gA_h = (const char*)(Qh + (size_t)(i0 + arow) * CC) + aq;
    const char* gA_l = (const char*)(Ql + (size_t)(i0 + arow) * CC) + aq;
    uint32_t s_a = sb + arow * 80 + aq;
    int brow = tid >> 1, bhalf = (tid & 1) * 32;
    const char* gB_h = (const char*)(Kh + (size_t)(j0 + brow) * CC) + bhalf;
    const char* gB_l = (const char*)(Kl + (size_t)(j0 + brow) * CC) + bhalf;
    uint32_t s_b = sb + B_OFF + brow * 80 + bhalf;

    uint32_t a_off = (wm * 32 + (lane & 15)) * 80 + ((lane >> 4) << 4);
    uint32_t b_off = (wn * 64 + (lane & 7) + ((lane >> 4) << 3)) * 80
                   + (((lane >> 3) & 1) << 4) + B_OFF;

    float acc[2][8][4];
#pragma unroll
    for (int i = 0; i < 2; i++)
#pragma unroll
        for (int j = 0; j < 8; j++)
#pragma unroll
            for (int r = 0; r < 4; r++) acc[i][j][r] = 0.0f;

    ISSUE_AB(0, 0);
    ISSUE_AB(STG, 64);
    uint32_t bA = 0, bB = STG, bC = 2 * STG;
    for (int ch = 0; ch < 8; ch++) {
        if (ch < 7) CP_WAIT1(); else CP_WAIT0();
        __syncthreads();
        if (ch < 6) ISSUE_AB(bC, (size_t)(ch + 2) * 64);
        mma_stage3(sb + bA, a_off, b_off, acc);
        uint32_t tmp = bA; bA = bB; bB = bC; bC = tmp;
    }

#pragma unroll
    for (int mi = 0; mi < 2; mi++) {
        int row = i0 + wm * 32 + mi * 16 + (lane >> 2);
#pragma unroll
        for (int np = 0; np < 8; np++) {
            int col = j0 + wn * 64 + np * 8 + (lane & 3) * 2;
            *(float2*)(S + (size_t)row * NN + col) =
                make_float2(acc[mi][np][0], acc[mi][np][1]);
            *(float2*)(S + (size_t)(row + 8) * NN + col) =
                make_float2(acc[mi][np][2], acc[mi][np][3]);
        }
    }

    int q = lane >> 2, qt = lane & 3;
    float mloc[2][2];
#pragma unroll
    for (int mi = 0; mi < 2; mi++)
#pragma unroll
        for (int rh = 0; rh < 2; rh++) {
            float m = -1e30f;
#pragma unroll
            for (int np = 0; np < 8; np++)
                m = fmaxf(m, fmaxf(acc[mi][np][rh * 2], acc[mi][np][rh * 2 + 1]));
            mloc[mi][rh] = m;
        }
#pragma unroll
    for (int d = 1; d <= 2; d <<= 1)
#pragma unroll
        for (int mi = 0; mi < 2; mi++)
#pragma unroll
            for (int rh = 0; rh < 2; rh++)
                mloc[mi][rh] = fmaxf(mloc[mi][rh],
                                     __shfl_xor_sync(0xffffffffu, mloc[mi][rh], d));
    if (qt == 0)
#pragma unroll
        for (int mi = 0; mi < 2; mi++)
#pragma unroll
            for (int rh = 0; rh < 2; rh++)
                pm[wm * 32 + mi * 16 + rh * 8 + q][wn] = mloc[mi][rh];
    __syncthreads();
    float mrow[2][2], srow[2][2];
#pragma unroll
    for (int mi = 0; mi < 2; mi++)
#pragma unroll
        for (int rh = 0; rh < 2; rh++) {
            int row = wm * 32 + mi * 16 + rh * 8 + q;
            float m = fmaxf(fmaxf(pm[row][0], pm[row][1]),
                            fmaxf(pm[row][2], pm[row][3]));
            mrow[mi][rh] = m;
            float s = 0.0f;
#pragma unroll
            for (int np = 0; np < 8; np++)
                s += fast_exp(acc[mi][np][rh * 2] - m)
                   + fast_exp(acc[mi][np][rh * 2 + 1] - m);
            srow[mi][rh] = s;
        }
#pragma unroll
    for (int d = 1; d <= 2; d <<= 1)
#pragma unroll
        for (int mi = 0; mi < 2; mi++)
#pragma unroll
            for (int rh = 0; rh < 2; rh++)
                srow[mi][rh] += __shfl_xor_sync(0xffffffffu, srow[mi][rh], d);
    if (qt == 0)
#pragma unroll
        for (int mi = 0; mi < 2; mi++)
#pragma unroll
            for (int rh = 0; rh < 2; rh++)
                pl[wm * 32 + mi * 16 + rh * 8 + q][wn] = srow[mi][rh];
    __syncthreads();
    if (qt == 0 && wn == 0)
#pragma unroll
        for (int mi = 0; mi < 2; mi++)
#pragma unroll
            for (int rh = 0; rh < 2; rh++) {
                int row = wm * 32 + mi * 16 + rh * 8 + q;
                size_t idx = ((size_t)b * NN + i0 + row) * 16 + blockIdx.y;
                g_pm[idx] = mrow[mi][rh];
                g_pl[idx] = pl[row][0] + pl[row][1] + pl[row][2] + pl[row][3];
            }
}

__global__ __launch_bounds__(256) void merge_kernel()
{
    int row = blockIdx.x * 16 + (threadIdx.x >> 4);
    int sub = threadIdx.x & 15;
    float m_t = g_pm[(size_t)row * 16 + sub];
    float l_t = g_pl[(size_t)row * 16 + sub];
    float m = m_t;
#pragma unroll
    for (int d = 8; d > 0; d >>= 1) m = fmaxf(m, __shfl_xor_sync(0xffffffffu, m, d));
    float l = l_t * fast_exp(m_t - m);
#pragma unroll
    for (int d = 8; d > 0; d >>= 1) l += __shfl_xor_sync(0xffffffffu, l, d);
    if (sub == 0) { g_m[row] = m; g_li[row] = 1.0f / l; }
}

// ---------------------------------------------------------------------------
// Kernel: PV, 2-term (P fp16 hi/lo x V fp16). 3-stage, 1 sync/chunk.
// grid (32, 1, 4), 512 threads. Writes out[b][c][i] directly.
// ---------------------------------------------------------------------------
__global__ void __launch_bounds__(512, 1) pv_mma(float* __restrict__ out)
{
    extern __shared__ char sm[];
    __shared__ float m_s[128], li_s[128];
    uint32_t sb = smem_u32(sm);
    int tid = threadIdx.x, wid = tid >> 5, lane = tid & 31;
    int b = blockIdx.z, i0 = blockIdx.x * 128;
    int wm = wid & 3, wn = wid >> 2;

    const float* S = g_s + (size_t)b * NN * NN;
    const __half* V = g_vt + (size_t)b * CC * NN;

    if (tid < 128) {
        m_s[tid]  = g_m[b * NN + i0 + tid];
        li_s[tid] = g_li[b * NN + i0 + tid];
    }

    // A producer: 8 P elements per thread (row=tid>>2, 8-col group=tid&3)
    int arow = tid >> 2, aq = tid & 3;
    const float* gS = S + (size_t)(i0 + arow) * NN + aq * 8;
    uint32_t s_aw_off = (uint32_t)arow * 80 + aq * 16;   // within stage

    // B loader: V tile 256 rows x 64B, thread covers 32B
    int brow = tid >> 1, bhalf = (tid & 1) * 32;
    const char* gv = (const char*)(V + (size_t)brow * NN) + bhalf;
    uint32_t s_b = sb + PB_OFF + brow * 80 + bhalf;

    uint32_t a_off = (wm * 32 + (lane & 15)) * 80 + ((lane >> 4) << 4);
    uint32_t b_off = (wn * 64 + (lane & 7) + ((lane >> 4) << 3)) * 80
                   + (((lane >> 3) & 1) << 4) + PB_OFF;

    float acc[2][8][4];
#pragma unroll
    for (int i = 0; i < 2; i++)
#pragma unroll
        for (int j = 0; j < 8; j++)
#pragma unroll
            for (int r = 0; r < 4; r++) acc[i][j][r] = 0.0f;

#define ISSUE_V(stg_base, goff) do {                              \
        uint32_t d = s_b + (stg_base);                            \
        CP16(d,      gv + (goff));                                \
        CP16(d + 16, gv + (goff) + 16);                           \
        CP_COMMIT();                                              \
    } while (0)

#define PRODUCE_A(stg_base) do {                                            \
        union { __half e[8]; uint4 v; } uh, ul;                             \
        _Pragma("unroll")                                                   \
        for (int u = 0; u < 2; u++) {                                       \
            float e0 = fast_exp(sv[u].x - mrow);                            \
            float e1 = fast_exp(sv[u].y - mrow);                            \
            float e2 = fast_exp(sv[u].z - mrow);                            \
            float e3 = fast_exp(sv[u].w - mrow);                            \
            f16_split(e0, uh.e[u * 4 + 0], ul.e[u * 4 + 0]);                \
            f16_split(e1, uh.e[u * 4 + 1], ul.e[u * 4 + 1]);                \
            f16_split(e2, uh.e[u * 4 + 2], ul.e[u * 4 + 2]);                \
            f16_split(e3, uh.e[u * 4 + 3], ul.e[u * 4 + 3]);                \
        }                                                                   \
        uint32_t doff = s_aw_off + (stg_base);                              \
        *(uint4*)(sm + doff)         = uh.v;                                \
        *(uint4*)(sm + doff + PA_LO) = ul.v;                                \
    } while (0)

    // Prologue
    float4 sv[2];
    {
        const float4* p = (const float4*)gS;
        sv[0] = p[0]; sv[1] = p[1];          // S(chunk 0)
    }
    ISSUE_V(0, 0);
    ISSUE_V(PSTG, 64);
    __syncthreads();                          // m_s visible
    float mrow = m_s[arow];
    PRODUCE_A(0);                             // A(0) -> stage0
    {
        const float4* p = (const float4*)(gS + 32);
        sv[0] = p[0]; sv[1] = p[1];          // S(chunk 1)
    }

    uint32_t bA = 0, bB = PSTG, bC = 2 * PSTG;
    for (int ch = 0; ch < 128; ch++) {
        if (ch < 127) CP_WAIT1(); else CP_WAIT0();
        __syncthreads();                      // B(ch) + A(ch) visible; stage bC free
        if (ch < 127) PRODUCE_A(bB);          // A(ch+1)
        if (ch < 126) {
            ISSUE_V(bC, (size_t)(ch + 2) * 64);
            const float4* p = (const float4*)(gS + (size_t)(ch + 2) * 32);
            sv[0] = p[0]; sv[1] = p[1];      // S(ch+2)
        }
        mma_stage2(sb + bA, a_off, b_off, acc);
        uint32_t tmp = bA; bA = bB; bB = bC; bC = tmp;
    }
#undef ISSUE_V
#undef PRODUCE_A

    // Epilogue: scale by 1/l, transpose 2x(128c x 128i) via smem, write out.
    float* smt = (float*)sm;
#pragma unroll
    for (int h = 0; h < 2; h++) {
        __syncthreads();
        if ((wn >> 1) == h) {
#pragma unroll
            for (int mi = 0; mi < 2; mi++) {
                int r0 = wm * 32 + mi * 16 + (lane >> 2);
                float l0 = li_s[r0], l1 = li_s[r0 + 8];
#pragma unroll
                for (int np = 0; np < 8; np++) {
                    int c = (wn & 1) * 64 + np * 8 + (lane & 3) * 2;
                    smt[(c + 0) * 132 + r0]     = acc[mi][np][0] * l0;
                    smt[(c + 1) * 132 + r0]     = acc[mi][np][1] * l0;
                    smt[(c + 0) * 132 + r0 + 8] = acc[mi][np][2] * l1;
                    smt[(c + 1) * 132 + r0 + 8] = acc[mi][np][3] * l1;
                }
            }
        }
        __syncthreads();
        {
            int cl = tid >> 2, part = tid & 3;
            float* op = out + ((size_t)b * CC + h * 128 + cl) * NN + i0 + part * 32;
            const float* sp = smt + cl * 132 + part * 32;
#pragma unroll
            for (int u = 0; u < 8; u++)
                ((float4*)op)[u] = ((const float4*)sp)[u];
        }
    }
}

extern "C" void kernel_launch(void* const* d_in, const int* in_sizes, int n_in,
                              void* d_out, int out_size)
{
    const float* x1 = (const float*)d_in[0];
    const float* x2 = (const float*)d_in[1];
    const float* Wq = (const float*)d_in[2];
    const float* bq = (const float*)d_in[3];
    const float* Wk = (const float*)d_in[4];
    const float* bk = (const float*)d_in[5];
    const float* Wv = (const float*)d_in[6];
    const float* bv = (const float*)d_in[7];
    float* out = (float*)d_out;

    cudaFuncSetAttribute(proj_mma,   cudaFuncAttributeMaxDynamicSharedMemorySize, SMEM_S);
    cudaFuncSetAttribute(scores_mma, cudaFuncAttributeMaxDynamicSharedMemorySize, SMEM_S);
    cudaFuncSetAttribute(pv_mma,     cudaFuncAttributeMaxDynamicSharedMemorySize, SMEM_P);

    wsplit_kernel<<<dim3(256, 3), 256>>>(Wq, Wk, Wv);
    bias_copy_kernel<<<1, 256>>>(bq, bk, bv);
    xprep_kernel<<<dim3(NN / 32, CC / 32, 2 * BB), dim3(32, 8)>>>(x1, x2);
    proj_mma<<<dim3(NN / 128, 1, BB * 3), 512, SMEM_S>>>();
    scores_mma<<<dim3(NN / 128, NN / 256, BB), 512, SMEM_S>>>();
    merge_kernel<<<BB * NN / 16, 256>>>();
    pv_mma<<<dim3(NN / 128, 1, BB), 512, SMEM_P>>>(out);
}

// round 7
// speedup vs baseline: 3.4396x; 1.1449x over previous
#include <cuda_runtime.h>
#include <cuda_fp16.h>
#include <cstdint>

#define BB 4
#define CC 256
#define NN 4096

// ---------------------------------------------------------------------------
// Scratch (allocation-free: __device__ bss). All operands fp16.
// ---------------------------------------------------------------------------
__device__ __half g_x1h[(size_t)BB * NN * CC];
__device__ __half g_x1l[(size_t)BB * NN * CC];
__device__ __half g_x2h[(size_t)BB * NN * CC];
__device__ __half g_x2l[(size_t)BB * NN * CC];
__device__ __half g_wh[3 * CC * CC];
__device__ __half g_wl[3 * CC * CC];
__device__ float  g_bias[3 * CC];
__device__ __half g_qh[(size_t)BB * NN * CC];
__device__ __half g_ql[(size_t)BB * NN * CC];
__device__ __half g_kh[(size_t)BB * NN * CC];
__device__ __half g_kl[(size_t)BB * NN * CC];
__device__ __half g_vt[(size_t)BB * CC * NN];     // V^T single fp16 [b][c][j]
__device__ float g_s[(size_t)BB * NN * NN];       // scores fp32 (256 MB)
__device__ float g_pm[(size_t)BB * NN * 16];
__device__ float g_pl[(size_t)BB * NN * 16];
__device__ float g_m [BB * NN];
__device__ float g_li[BB * NN];

// ---------------------------------------------------------------------------
// PTX helpers
// ---------------------------------------------------------------------------
__device__ __forceinline__ uint32_t smem_u32(const void* p) {
    uint32_t a;
    asm("{ .reg .u64 t; cvta.to.shared.u64 t, %1; cvt.u32.u64 %0, t; }"
        : "=r"(a) : "l"(p));
    return a;
}

#define CP16(smem, gptr) \
    asm volatile("cp.async.ca.shared.global [%0], [%1], 16;" \
                 :: "r"(smem), "l"(gptr) : "memory")
#define CP_COMMIT() asm volatile("cp.async.commit_group;" ::: "memory")
#define CP_WAIT1()  asm volatile("cp.async.wait_group 1;" ::: "memory")
#define CP_WAIT0()  asm volatile("cp.async.wait_group 0;" ::: "memory")

#define LDSM4(r0, r1, r2, r3, addr) \
    asm volatile("ldmatrix.sync.aligned.m8n8.x4.shared.b16 {%0,%1,%2,%3}, [%4];" \
                 : "=r"(r0), "=r"(r1), "=r"(r2), "=r"(r3) : "r"(addr))

__device__ __forceinline__ void mma_f16(float* d, const uint32_t* a,
                                        uint32_t b0, uint32_t b1) {
    asm volatile(
        "mma.sync.aligned.m16n8k16.row.col.f32.f16.f16.f32 "
        "{%0,%1,%2,%3}, {%4,%5,%6,%7}, {%8,%9}, {%0,%1,%2,%3};"
        : "+f"(d[0]), "+f"(d[1]), "+f"(d[2]), "+f"(d[3])
        : "r"(a[0]), "r"(a[1]), "r"(a[2]), "r"(a[3]), "r"(b0), "r"(b1));
}

// k-chunk 32 fp16, 80B-padded rows (conflict-free ldmatrix).
// scores/proj stage: Ah(10240) Al(10240) Bh(20480) Bl(20480) = 61440, x3
#define A_LO    10240
#define B_OFF   20480
#define B_LO    20480
#define STG     61440
#define SMEM_S  (3 * STG)      // 184320
// pv stage (1-term): Ph(10240) V(20480) = 30720, x3
#define PB_OFF  10240
#define PSTG    30720
#define SMEM_P  (3 * PSTG)     // 92160

__device__ __forceinline__ float fast_exp(float x) {
    float y = fmaxf(x, -87.0f) * 1.4426950408889634f;
    float z = __fadd_rn(y, 12582912.0f);
    int   k = __float_as_int(z) - 0x4B400000;
    float f = __fsub_rn(y, __fsub_rn(z, 12582912.0f));
    float p =             1.33335581e-3f;
    p = fmaf(p, f, 9.61812910e-3f);
    p = fmaf(p, f, 5.55041087e-2f);
    p = fmaf(p, f, 2.40226507e-1f);
    p = fmaf(p, f, 6.93147181e-1f);
    p = fmaf(p, f, 1.0f);
    return __int_as_float(__float_as_int(p) + (k << 23));
}

__device__ __forceinline__ void f16_split(float v, __half& h, __half& l) {
    h = __float2half_rn(v);
    l = __float2half_rn(v - __half2float(h));
}

// ---------------------------------------------------------------------------
// Prep kernels
// ---------------------------------------------------------------------------
__global__ void wsplit_kernel(const float* __restrict__ Wq,
                              const float* __restrict__ Wk,
                              const float* __restrict__ Wv)
{
    int t = blockIdx.y;
    const float* W = (t == 0) ? Wq : (t == 1) ? Wk : Wv;
    int idx = blockIdx.x * 256 + threadIdx.x;
    float v = W[idx];
    __half h, l;
    f16_split(v, h, l);
    g_wh[t * CC * CC + idx] = h;
    g_wl[t * CC * CC + idx] = l;
}

__global__ void bias_copy_kernel(const float* __restrict__ bq,
                                 const float* __restrict__ bk,
                                 const float* __restrict__ bv)
{
    int i = threadIdx.x;
    g_bias[i]          = bq[i];
    g_bias[CC + i]     = bk[i];
    g_bias[2 * CC + i] = bv[i];
}

__global__ void xprep_kernel(const float* __restrict__ x1,
                             const float* __restrict__ x2)
{
    __shared__ float tile[32][33];
    int z = blockIdx.z;
    int b = z & 3;
    const float* src = ((z < 4) ? x1 : x2) + (size_t)b * CC * NN;
    __half* dh = ((z < 4) ? g_x1h : g_x2h) + (size_t)b * NN * CC;
    __half* dl = ((z < 4) ? g_x1l : g_x2l) + (size_t)b * NN * CC;
    int i0 = blockIdx.x * 32;
    int c0 = blockIdx.y * 32;
    int tx = threadIdx.x, ty = threadIdx.y;
#pragma unroll
    for (int u = 0; u < 32; u += 8)
        tile[ty + u][tx] = src[(size_t)(c0 + ty + u) * NN + i0 + tx];
    __syncthreads();
#pragma unroll
    for (int u = 0; u < 32; u += 8) {
        float v = tile[tx][ty + u];
        __half h, l;
        f16_split(v, h, l);
        size_t idx = (size_t)(i0 + ty + u) * CC + c0 + tx;
        dh[idx] = h;
        dl[idx] = l;
    }
}

// ---------------------------------------------------------------------------
// Warp MMA: 3-term (A hi/lo x B hi/lo, drop lo*lo), warp tile 32x64.
// ---------------------------------------------------------------------------
__device__ __forceinline__ void mma_stage3(uint32_t st, uint32_t a_off, uint32_t b_off,
                                           float acc[2][8][4])
{
#pragma unroll
    for (int kk = 0; kk < 2; kk++) {
        uint32_t ah[2][4], al[2][4];
#pragma unroll
        for (int mi = 0; mi < 2; mi++) {
            uint32_t ad = st + a_off + mi * (16 * 80) + kk * 32;
            LDSM4(ah[mi][0], ah[mi][1], ah[mi][2], ah[mi][3], ad);
            LDSM4(al[mi][0], al[mi][1], al[mi][2], al[mi][3], ad + A_LO);
        }
#pragma unroll
        for (int ng = 0; ng < 4; ng++) {
            uint32_t bd = st + b_off + ng * (16 * 80) + kk * 32;
            uint32_t bh[4], bl[4];
            LDSM4(bh[0], bh[1], bh[2], bh[3], bd);
            LDSM4(bl[0], bl[1], bl[2], bl[3], bd + B_LO);
#pragma unroll
            for (int mi = 0; mi < 2; mi++) {
                mma_f16(acc[mi][ng * 2],     ah[mi], bh[0], bh[1]);
                mma_f16(acc[mi][ng * 2 + 1], ah[mi], bh[2], bh[3]);
                mma_f16(acc[mi][ng * 2],     ah[mi], bl[0], bl[1]);
                mma_f16(acc[mi][ng * 2 + 1], ah[mi], bl[2], bl[3]);
                mma_f16(acc[mi][ng * 2],     al[mi], bh[0], bh[1]);
                mma_f16(acc[mi][ng * 2 + 1], al[mi], bh[2], bh[3]);
            }
        }
    }
}

// 1-term PV: P(single fp16) x V(single fp16).
__device__ __forceinline__ void mma_stage1(uint32_t st, uint32_t a_off, uint32_t b_off,
                                           float acc[2][8][4])
{
#pragma unroll
    for (int kk = 0; kk < 2; kk++) {
        uint32_t ah[2][4];
#pragma unroll
        for (int mi = 0; mi < 2; mi++) {
            uint32_t ad = st + a_off + mi * (16 * 80) + kk * 32;
            LDSM4(ah[mi][0], ah[mi][1], ah[mi][2], ah[mi][3], ad);
        }
#pragma unroll
        for (int ng = 0; ng < 4; ng++) {
            uint32_t bd = st + b_off + ng * (16 * 80) + kk * 32;
            uint32_t bh[4];
            LDSM4(bh[0], bh[1], bh[2], bh[3], bd);
#pragma unroll
            for (int mi = 0; mi < 2; mi++) {
                mma_f16(acc[mi][ng * 2],     ah[mi], bh[0], bh[1]);
                mma_f16(acc[mi][ng * 2 + 1], ah[mi], bh[2], bh[3]);
            }
        }
    }
}

// Loader: A (128 rows x 64B hi+lo), B (256 rows x 64B hi+lo). 512 threads.
#define ISSUE_AB(stg_base, goff) do {                             \
        uint32_t dA = s_a + (stg_base);                           \
        uint32_t dB = s_b + (stg_base);                           \
        CP16(dA,             gA_h + (goff));                      \
        CP16(dA + A_LO,      gA_l + (goff));                      \
        CP16(dB,             gB_h + (goff));                      \
        CP16(dB + 16,        gB_h + (goff) + 16);                 \
        CP16(dB + B_LO,      gB_l + (goff));                      \
        CP16(dB + B_LO + 16, gB_l + (goff) + 16);                 \
        CP_COMMIT();                                              \
    } while (0)

// ---------------------------------------------------------------------------
// Kernel: QKV projection via mma (fp16 3-term). grid (32,1,12), 512 thr.
// ---------------------------------------------------------------------------
__global__ void __launch_bounds__(512, 1) proj_mma()
{
    extern __shared__ char sm[];
    __shared__ float bias_s[256];
    uint32_t sb = smem_u32(sm);
    int tid = threadIdx.x, wid = tid >> 5, lane = tid & 31;
    int z = blockIdx.z;
    int b = z / 3, t = z % 3;
    int i0 = blockIdx.x * 128;
    int wm = wid & 3, wn = wid >> 2;

    const __half* Xh = ((t == 0) ? g_x1h : g_x2h) + (size_t)b * NN * CC;
    const __half* Xl = ((t == 0) ? g_x1l : g_x2l) + (size_t)b * NN * CC;
    const __half* Wh = g_wh + t * CC * CC;
    const __half* Wl = g_wl + t * CC * CC;

    if (tid < 256) bias_s[tid] = g_bias[t * CC + tid];

    int arow = tid >> 2, aq = (tid & 3) * 16;
    const char* gA_h = (const char*)(Xh + (size_t)(i0 + arow) * CC) + aq;
    const char* gA_l = (const char*)(Xl + (size_t)(i0 + arow) * CC) + aq;
    uint32_t s_a = sb + arow * 80 + aq;
    int brow = tid >> 1, bhalf = (tid & 1) * 32;
    const char* gB_h = (const char*)(Wh + (size_t)brow * CC) + bhalf;
    const char* gB_l = (const char*)(Wl + (size_t)brow * CC) + bhalf;
    uint32_t s_b = sb + B_OFF + brow * 80 + bhalf;

    uint32_t a_off = (wm * 32 + (lane & 15)) * 80 + ((lane >> 4) << 4);
    uint32_t b_off = (wn * 64 + (lane & 7) + ((lane >> 4) << 3)) * 80
                   + (((lane >> 3) & 1) << 4) + B_OFF;

    float acc[2][8][4];
#pragma unroll
    for (int i = 0; i < 2; i++)
#pragma unroll
        for (int j = 0; j < 8; j++)
#pragma unroll
            for (int r = 0; r < 4; r++) acc[i][j][r] = 0.0f;

    ISSUE_AB(0, 0);
    ISSUE_AB(STG, 64);
    uint32_t bA = 0, bB = STG, bC = 2 * STG;
    for (int ch = 0; ch < 8; ch++) {
        if (ch < 7) CP_WAIT1(); else CP_WAIT0();
        __syncthreads();
        if (ch < 6) ISSUE_AB(bC, (size_t)(ch + 2) * 64);
        mma_stage3(sb + bA, a_off, b_off, acc);
        uint32_t tmp = bA; bA = bB; bB = bC; bC = tmp;
    }

    if (t < 2) {
        __half* dh = ((t == 0) ? g_qh : g_kh) + (size_t)b * NN * CC;
        __half* dl = ((t == 0) ? g_ql : g_kl) + (size_t)b * NN * CC;
#pragma unroll
        for (int mi = 0; mi < 2; mi++) {
#pragma unroll
            for (int np = 0; np < 8; np++) {
                int col = wn * 64 + np * 8 + (lane & 3) * 2;
                float bc0 = bias_s[col], bc1 = bias_s[col + 1];
#pragma unroll
                for (int rh = 0; rh < 2; rh++) {
                    int row = i0 + wm * 32 + mi * 16 + rh * 8 + (lane >> 2);
                    float v0 = acc[mi][np][rh * 2]     + bc0;
                    float v1 = acc[mi][np][rh * 2 + 1] + bc1;
                    __half h0, l0, h1, l1;
                    f16_split(v0, h0, l0);
                    f16_split(v1, h1, l1);
                    union { __half e[2]; uint32_t u; } ph, pl;
                    ph.e[0] = h0; ph.e[1] = h1;
                    pl.e[0] = l0; pl.e[1] = l1;
                    *(uint32_t*)(dh + (size_t)row * CC + col) = ph.u;
                    *(uint32_t*)(dl + (size_t)row * CC + col) = pl.u;
                }
            }
        }
    } else {
        __half* dv = g_vt + (size_t)b * CC * NN;
        float* smt = (float*)sm;
#pragma unroll
        for (int h = 0; h < 2; h++) {
            __syncthreads();
            if ((wn >> 1) == h) {
#pragma unroll
                for (int mi = 0; mi < 2; mi++) {
                    int r0 = wm * 32 + mi * 16 + (lane >> 2);
#pragma unroll
                    for (int np = 0; np < 8; np++) {
                        int cl = (wn & 1) * 64 + np * 8 + (lane & 3) * 2;
                        float b0 = bias_s[h * 128 + cl], b1 = bias_s[h * 128 + cl + 1];
                        smt[(cl + 0) * 132 + r0]     = acc[mi][np][0] + b0;
                        smt[(cl + 1) * 132 + r0]     = acc[mi][np][1] + b1;
                        smt[(cl + 0) * 132 + r0 + 8] = acc[mi][np][2] + b0;
                        smt[(cl + 1) * 132 + r0 + 8] = acc[mi][np][3] + b1;
                    }
                }
            }
            __syncthreads();
            {
                int cl = tid >> 2, part = tid & 3;
                const float* sp = smt + cl * 132 + part * 32;
                size_t go = (size_t)(h * 128 + cl) * NN + i0 + part * 32;
                union { __half e[32]; uint4 v[4]; } uh;
#pragma unroll
                for (int u = 0; u < 32; u++) uh.e[u] = __float2half_rn(sp[u]);
#pragma unroll
                for (int u = 0; u < 4; u++)
                    *(uint4*)(dv + go + u * 8) = uh.v[u];
            }
        }
    }
}

// ---------------------------------------------------------------------------
// Kernel: scores S = Q.K^T (fp16 3-term) + fused partial softmax stats.
// grid (32, 16, 4), 512 threads.
// ---------------------------------------------------------------------------
__global__ void __launch_bounds__(512, 1) scores_mma()
{
    extern __shared__ char sm[];
    __shared__ float pm[128][4], pl[128][4];
    uint32_t sb = smem_u32(sm);
    int tid = threadIdx.x, wid = tid >> 5, lane = tid & 31;
    int b = blockIdx.z, i0 = blockIdx.x * 128, j0 = blockIdx.y * 256;
    int wm = wid & 3, wn = wid >> 2;

    const __half* Qh = g_qh + (size_t)b * NN * CC;
    const __half* Ql = g_ql + (size_t)b * NN * CC;
    const __half* Kh = g_kh + (size_t)b * NN * CC;
    const __half* Kl = g_kl + (size_t)b * NN * CC;
    float* S = g_s + (size_t)b * NN * NN;

    int arow = tid >> 2, aq = (tid & 3) * 16;
    const char* gA_h = (const char*)(Qh + (size_t)(i0 + arow) * CC) + aq;
    const char* gA_l = (const char*)(Ql + (size_t)(i0 + arow) * CC) + aq;
    uint32_t s_a = sb + arow * 80 + aq;
    int brow = tid >> 1, bhalf = (tid & 1) * 32;
    const char* gB_h = (const char*)(Kh + (size_t)(j0 + brow) * CC) + bhalf;
    const char* gB_l = (const char*)(Kl + (size_t)(j0 + brow) * CC) + bhalf;
    uint32_t s_b = sb + B_OFF + brow * 80 + bhalf;

    uint32_t a_off = (wm * 32 + (lane & 15)) * 80 + ((lane >> 4) << 4);
    uint32_t b_off = (wn * 64 + (lane & 7) + ((lane >> 4) << 3)) * 80
                   + (((lane >> 3) & 1) << 4) + B_OFF;

    float acc[2][8][4];
#pragma unroll
    for (int i = 0; i < 2; i++)
#pragma unroll
        for (int j = 0; j < 8; j++)
#pragma unroll
            for (int r = 0; r < 4; r++) acc[i][j][r] = 0.0f;

    ISSUE_AB(0, 0);
    ISSUE_AB(STG, 64);
    uint32_t bA = 0, bB = STG, bC = 2 * STG;
    for (int ch = 0; ch < 8; ch++) {
        if (ch < 7) CP_WAIT1(); else CP_WAIT0();
        __syncthreads();
        if (ch < 6) ISSUE_AB(bC, (size_t)(ch + 2) * 64);
        mma_stage3(sb + bA, a_off, b_off, acc);
        uint32_t tmp = bA; bA = bB; bB = bC; bC = tmp;
    }

#pragma unroll
    for (int mi = 0; mi < 2; mi++) {
        int row = i0 + wm * 32 + mi * 16 + (lane >> 2);
#pragma unroll
        for (int np = 0; np < 8; np++) {
            int col = j0 + wn * 64 + np * 8 + (lane & 3) * 2;
            *(float2*)(S + (size_t)row * NN + col) =
                make_float2(acc[mi][np][0], acc[mi][np][1]);
            *(float2*)(S + (size_t)(row + 8) * NN + col) =
                make_float2(acc[mi][np][2], acc[mi][np][3]);
        }
    }

    int q = lane >> 2, qt = lane & 3;
    float mloc[2][2];
#pragma unroll
    for (int mi = 0; mi < 2; mi++)
#pragma unroll
        for (int rh = 0; rh < 2; rh++) {
            float m = -1e30f;
#pragma unroll
            for (int np = 0; np < 8; np++)
                m = fmaxf(m, fmaxf(acc[mi][np][rh * 2], acc[mi][np][rh * 2 + 1]));
            mloc[mi][rh] = m;
        }
#pragma unroll
    for (int d = 1; d <= 2; d <<= 1)
#pragma unroll
        for (int mi = 0; mi < 2; mi++)
#pragma unroll
            for (int rh = 0; rh < 2; rh++)
                mloc[mi][rh] = fmaxf(mloc[mi][rh],
                                     __shfl_xor_sync(0xffffffffu, mloc[mi][rh], d));
    if (qt == 0)
#pragma unroll
        for (int mi = 0; mi < 2; mi++)
#pragma unroll
            for (int rh = 0; rh < 2; rh++)
                pm[wm * 32 + mi * 16 + rh * 8 + q][wn] = mloc[mi][rh];
    __syncthreads();
    float mrow[2][2], srow[2][2];
#pragma unroll
    for (int mi = 0; mi < 2; mi++)
#pragma unroll
        for (int rh = 0; rh < 2; rh++) {
            int row = wm * 32 + mi * 16 + rh * 8 + q;
            float m = fmaxf(fmaxf(pm[row][0], pm[row][1]),
                            fmaxf(pm[row][2], pm[row][3]));
            mrow[mi][rh] = m;
            float s = 0.0f;
#pragma unroll
            for (int np = 0; np < 8; np++)
                s += fast_exp(acc[mi][np][rh * 2] - m)
                   + fast_exp(acc[mi][np][rh * 2 + 1] - m);
            srow[mi][rh] = s;
        }
#pragma unroll
    for (int d = 1; d <= 2; d <<= 1)
#pragma unroll
        for (int mi = 0; mi < 2; mi++)
#pragma unroll
            for (int rh = 0; rh < 2; rh++)
                srow[mi][rh] += __shfl_xor_sync(0xffffffffu, srow[mi][rh], d);
    if (qt == 0)
#pragma unroll
        for (int mi = 0; mi < 2; mi++)
#pragma unroll
            for (int rh = 0; rh < 2; rh++)
                pl[wm * 32 + mi * 16 + rh * 8 + q][wn] = srow[mi][rh];
    __syncthreads();
    if (qt == 0 && wn == 0)
#pragma unroll
        for (int mi = 0; mi < 2; mi++)
#pragma unroll
            for (int rh = 0; rh < 2; rh++) {
                int row = wm * 32 + mi * 16 + rh * 8 + q;
                size_t idx = ((size_t)b * NN + i0 + row) * 16 + blockIdx.y;
                g_pm[idx] = mrow[mi][rh];
                g_pl[idx] = pl[row][0] + pl[row][1] + pl[row][2] + pl[row][3];
            }
}

__global__ __launch_bounds__(256) void merge_kernel()
{
    int row = blockIdx.x * 16 + (threadIdx.x >> 4);
    int sub = threadIdx.x & 15;
    float m_t = g_pm[(size_t)row * 16 + sub];
    float l_t = g_pl[(size_t)row * 16 + sub];
    float m = m_t;
#pragma unroll
    for (int d = 8; d > 0; d >>= 1) m = fmaxf(m, __shfl_xor_sync(0xffffffffu, m, d));
    float l = l_t * fast_exp(m_t - m);
#pragma unroll
    for (int d = 8; d > 0; d >>= 1) l += __shfl_xor_sync(0xffffffffu, l, d);
    if (sub == 0) { g_m[row] = m; g_li[row] = 1.0f / l; }
}

// ---------------------------------------------------------------------------
// Kernel: PV, 1-term (P fp16 x V fp16). 3-stage, 1 sync/chunk.
// grid (32, 1, 4), 512 threads. Writes out[b][c][i] directly.
// ---------------------------------------------------------------------------
__global__ void __launch_bounds__(512, 1) pv_mma(float* __restrict__ out)
{
    extern __shared__ char sm[];
    __shared__ float m_s[128], li_s[128];
    uint32_t sb = smem_u32(sm);
    int tid = threadIdx.x, wid = tid >> 5, lane = tid & 31;
    int b = blockIdx.z, i0 = blockIdx.x * 128;
    int wm = wid & 3, wn = wid >> 2;

    const float* S = g_s + (size_t)b * NN * NN;
    const __half* V = g_vt + (size_t)b * CC * NN;

    if (tid < 128) {
        m_s[tid]  = g_m[b * NN + i0 + tid];
        li_s[tid] = g_li[b * NN + i0 + tid];
    }

    // A producer: 8 P elements per thread (row=tid>>2, 8-col group=tid&3)
    int arow = tid >> 2, aq = tid & 3;
    const float* gS = S + (size_t)(i0 + arow) * NN + aq * 8;
    uint32_t s_aw_off = (uint32_t)arow * 80 + aq * 16;   // within stage

    // B loader: V tile 256 rows x 64B, thread covers 32B
    int brow = tid >> 1, bhalf = (tid & 1) * 32;
    const char* gv = (const char*)(V + (size_t)brow * NN) + bhalf;
    uint32_t s_b = sb + PB_OFF + brow * 80 + bhalf;

    uint32_t a_off = (wm * 32 + (lane & 15)) * 80 + ((lane >> 4) << 4);
    uint32_t b_off = (wn * 64 + (lane & 7) + ((lane >> 4) << 3)) * 80
                   + (((lane >> 3) & 1) << 4) + PB_OFF;

    float acc[2][8][4];
#pragma unroll
    for (int i = 0; i < 2; i++)
#pragma unroll
        for (int j = 0; j < 8; j++)
#pragma unroll
            for (int r = 0; r < 4; r++) acc[i][j][r] = 0.0f;

#define ISSUE_V(stg_base, goff) do {                              \
        uint32_t d = s_b + (stg_base);                            \
        CP16(d,      gv + (goff));                                \
        CP16(d + 16, gv + (goff) + 16);                           \
        CP_COMMIT();                                              \
    } while (0)

#define PRODUCE_A(stg_base) do {                                            \
        union { __half e[8]; uint4 v; } uh;                                 \
        _Pragma("unroll")                                                   \
        for (int u = 0; u < 2; u++) {                                       \
            uh.e[u * 4 + 0] = __float2half_rn(fast_exp(sv[u].x - mrow));    \
            uh.e[u * 4 + 1] = __float2half_rn(fast_exp(sv[u].y - mrow));    \
            uh.e[u * 4 + 2] = __float2half_rn(fast_exp(sv[u].z - mrow));    \
            uh.e[u * 4 + 3] = __float2half_rn(fast_exp(sv[u].w - mrow));    \
        }                                                                   \
        *(uint4*)(sm + s_aw_off + (stg_base)) = uh.v;                       \
    } while (0)

    // Prologue
    float4 sv[2];
    {
        const float4* p = (const float4*)gS;
        sv[0] = p[0]; sv[1] = p[1];          // S(chunk 0)
    }
    ISSUE_V(0, 0);
    ISSUE_V(PSTG, 64);
    __syncthreads();                          // m_s visible
    float mrow = m_s[arow];
    PRODUCE_A(0);                             // A(0) -> stage0
    {
        const float4* p = (const float4*)(gS + 32);
        sv[0] = p[0]; sv[1] = p[1];          // S(chunk 1)
    }

    uint32_t bA = 0, bB = PSTG, bC = 2 * PSTG;
    for (int ch = 0; ch < 128; ch++) {
        if (ch < 127) CP_WAIT1(); else CP_WAIT0();
        __syncthreads();                      // B(ch) + A(ch) visible; stage bC free
        if (ch < 127) PRODUCE_A(bB);          // A(ch+1)
        if (ch < 126) {
            ISSUE_V(bC, (size_t)(ch + 2) * 64);
            const float4* p = (const float4*)(gS + (size_t)(ch + 2) * 32);
            sv[0] = p[0]; sv[1] = p[1];      // S(ch+2)
        }
        mma_stage1(sb + bA, a_off, b_off, acc);
        uint32_t tmp = bA; bA = bB; bB = bC; bC = tmp;
    }
#undef ISSUE_V
#undef PRODUCE_A

    // Epilogue: scale by 1/l, transpose 2x(128c x 128i) via smem, write out.
    float* smt = (float*)sm;
#pragma unroll
    for (int h = 0; h < 2; h++) {
        __syncthreads();
        if ((wn >> 1) == h) {
#pragma unroll
            for (int mi = 0; mi < 2; mi++) {
                int r0 = wm * 32 + mi * 16 + (lane >> 2);
                float l0 = li_s[r0], l1 = li_s[r0 + 8];
#pragma unroll
                for (int np = 0; np < 8; np++) {
                    int c = (wn & 1) * 64 + np * 8 + (lane & 3) * 2;
                    smt[(c + 0) * 132 + r0]     = acc[mi][np][0] * l0;
                    smt[(c + 1) * 132 + r0]     = acc[mi][np][1] * l0;
                    smt[(c + 0) * 132 + r0 + 8] = acc[mi][np][2] * l1;
                    smt[(c + 1) * 132 + r0 + 8] = acc[mi][np][3] * l1;
                }
            }
        }
        __syncthreads();
        {
            int cl = tid >> 2, part = tid & 3;
            float* op = out + ((size_t)b * CC + h * 128 + cl) * NN + i0 + part * 32;
            const float* sp = smt + cl * 132 + part * 32;
#pragma unroll
            for (int u = 0; u < 8; u++)
                ((float4*)op)[u] = ((const float4*)sp)[u];
        }
    }
}

extern "C" void kernel_launch(void* const* d_in, const int* in_sizes, int n_in,
                              void* d_out, int out_size)
{
    const float* x1 = (const float*)d_in[0];
    const float* x2 = (const float*)d_in[1];
    const float* Wq = (const float*)d_in[2];
    const float* bq = (const float*)d_in[3];
    const float* Wk = (const float*)d_in[4];
    const float* bk = (const float*)d_in[5];
    const float* Wv = (const float*)d_in[6];
    const float* bv = (const float*)d_in[7];
    float* out = (float*)d_out;

    cudaFuncSetAttribute(proj_mma,   cudaFuncAttributeMaxDynamicSharedMemorySize, SMEM_S);
    cudaFuncSetAttribute(scores_mma, cudaFuncAttributeMaxDynamicSharedMemorySize, SMEM_S);
    cudaFuncSetAttribute(pv_mma,     cudaFuncAttributeMaxDynamicSharedMemorySize, SMEM_P);

    wsplit_kernel<<<dim3(256, 3), 256>>>(Wq, Wk, Wv);
    bias_copy_kernel<<<1, 256>>>(bq, bk, bv);
    xprep_kernel<<<dim3(NN / 32, CC / 32, 2 * BB), dim3(32, 8)>>>(x1, x2);
    proj_mma<<<dim3(NN / 128, 1, BB * 3), 512, SMEM_S>>>();
    scores_mma<<<dim3(NN / 128, NN / 256, BB), 512, SMEM_S>>>();
    merge_kernel<<<BB * NN / 16, 256>>>();
    pv_mma<<<dim3(NN / 128, 1, BB), 512, SMEM_P>>>(out);
}